// round 6
// baseline (speedup 1.0000x reference)
#include <cuda_runtime.h>
#include <cstdint>
#include <math.h>

// ---------------------------------------------------------------------------
// SpatialBayesianLayer: BitLinear(2F->F) -> ReLU -> BitLinear(F->F) -> sigmoid
//                       -> posterior = prior*lik / sum_S(prior*lik)
// Exact-int8 tensor-core implementation (mma.sync m16n8k32.s8).
// R4: split latency-hostile activation quantization into its own streaming
//     kernel (global int8 XQ + scales); main kernel consumes XQ via cp.async.
// ---------------------------------------------------------------------------

#define QBF 127.0f
#define EPSF 1e-5f

#define NTOK   262144          // 8 * 32768 tokens
// ---- device scratch (no runtime allocation allowed) ----
__device__ unsigned char g_XQ[NTOK * 256];   // quantized [prior|evidence] rows
__device__ float  g_s1[NTOK];                // per-token act scale (QB/absmax)
__device__ int8_t g_W1q[128 * 256];
__device__ int8_t g_W2q[128 * 128];
__device__ float  g_wsc[2];        // mean |w| per layer (ref's 1/ws)
__device__ double g_norm[1024];    // per (batch, feature) normalizer accumulators
__device__ float  g_rnorm[1024];   // reciprocal normalizers

// ---- shared memory layout for bitnet_B (bytes) ----
// XQ : 128 x 256 int8, row stride 272 (68 words, 68%32==4 -> conflict-free frags)
//      (HQ [128 x 128] aliases bytes 0..143 of each XQ row after GEMM1; bands
//       are warp-private so __syncwarp suffices)
// W1 : 128 x 256 int8, stride 272
// W2 : 128 x 128 int8, stride 144
#define OFF_XQ     0
#define XQ_STR     272
#define OFF_W1     34816
#define W1_STR     272
#define OFF_W2     69632
#define W2_STR     144
#define OFF_S1     88064
#define OFF_B1     88576
#define OFF_B2     89088
#define OFF_CS     89600
#define SMEM_BYTES 90112

// ---------------------------------------------------------------------------
__device__ __forceinline__ void mma_s8(int* c,
                                       unsigned a0, unsigned a1, unsigned a2, unsigned a3,
                                       unsigned b0, unsigned b1) {
    asm volatile(
        "mma.sync.aligned.m16n8k32.row.col.s32.s8.s8.s32 "
        "{%0,%1,%2,%3}, {%4,%5,%6,%7}, {%8,%9}, {%0,%1,%2,%3};"
        : "+r"(c[0]), "+r"(c[1]), "+r"(c[2]), "+r"(c[3])
        : "r"(a0), "r"(a1), "r"(a2), "r"(a3), "r"(b0), "r"(b1));
}

__device__ __forceinline__ void cp16(uint32_t dst, const void* src) {
    asm volatile("cp.async.cg.shared.global [%0], [%1], 16;" :: "r"(dst), "l"(src));
}

__device__ __forceinline__ uint32_t smem_u32(const void* p) {
    uint32_t a;
    asm("{ .reg .u64 t; cvta.to.shared.u64 t, %1; cvt.u32.u64 %0, t; }"
        : "=r"(a) : "l"(p));
    return a;
}

__device__ __forceinline__ int clamp_q(int q) {
    return q < -128 ? -128 : (q > 127 ? 127 : q);
}

__device__ __forceinline__ unsigned pack_q4(float4 v, float s) {
    int q0 = clamp_q(__float2int_rn(v.x * s));
    int q1 = clamp_q(__float2int_rn(v.y * s));
    int q2 = clamp_q(__float2int_rn(v.z * s));
    int q3 = clamp_q(__float2int_rn(v.w * s));
    return (unsigned)(q0 & 255) | ((unsigned)(q1 & 255) << 8) |
           ((unsigned)(q2 & 255) << 16) | ((unsigned)(q3 & 255) << 24);
}

// ---------------------------------------------------------------------------
// Kernel 1: weight ternarization (absmean scale) + zero normalizers.
// ---------------------------------------------------------------------------
__global__ void prep_kernel(const float* __restrict__ W1,
                            const float* __restrict__ W2) {
    __shared__ double red[1024];
    __shared__ float s_ws;
    const int tid = threadIdx.x;
    const float* W = (blockIdx.x == 0) ? W1 : W2;
    int8_t* Wq     = (blockIdx.x == 0) ? g_W1q : g_W2q;
    const int n    = (blockIdx.x == 0) ? 128 * 256 : 128 * 128;

    if (tid < 512) g_norm[blockIdx.x * 512 + tid] = 0.0;

    double acc = 0.0;
    for (int i = tid; i < n; i += 1024) acc += (double)fabsf(W[i]);
    red[tid] = acc;
    __syncthreads();
    for (int s = 512; s > 0; s >>= 1) {
        if (tid < s) red[tid] += red[tid + s];
        __syncthreads();
    }
    if (tid == 0) {
        float m  = fmaxf((float)(red[0] / (double)n), EPSF);
        s_ws = 1.0f / m;                 // ref: ws = 1/clip(mean)
        g_wsc[blockIdx.x] = m;           // ref's t/ws (t = +-1) -> t*m
    }
    __syncthreads();
    const float ws = s_ws;
    for (int i = tid; i < n; i += 1024) {
        float t = rintf(W[i] * ws);      // round half-to-even like jnp.round
        t = fminf(1.0f, fmaxf(-1.0f, t));
        Wq[i] = (int8_t)t;
    }
}

// ---------------------------------------------------------------------------
// Kernel 2: streaming activation quantization. 1 warp per token row,
// 8 rows per warp, all loads front-batched (MLP=16).
// ---------------------------------------------------------------------------
__global__ __launch_bounds__(256)
void quant_kernel(const float* __restrict__ evid, const float* __restrict__ prior) {
    const int lane = threadIdx.x & 31;
    const int w    = threadIdx.x >> 5;
    const int r0   = blockIdx.x * 64 + w * 8;   // 4096 blocks * 8 warps * 8 rows

    const float4* pr4 = (const float4*)prior;
    const float4* ev4 = (const float4*)evid;
    unsigned* xq = (unsigned*)g_XQ;

    float4 pa[8], ea[8];
#pragma unroll
    for (int r = 0; r < 8; r++) {
        pa[r] = __ldg(&pr4[(size_t)(r0 + r) * 32 + lane]);
        ea[r] = __ldg(&ev4[(size_t)(r0 + r) * 32 + lane]);
    }
#pragma unroll
    for (int r = 0; r < 8; r++) {
        float4 a = pa[r], b = ea[r];
        float m = fmaxf(fmaxf(fabsf(a.x), fabsf(a.y)), fmaxf(fabsf(a.z), fabsf(a.w)));
        m = fmaxf(m, fmaxf(fmaxf(fabsf(b.x), fabsf(b.y)), fmaxf(fabsf(b.z), fabsf(b.w))));
        m = fmaxf(m, __shfl_xor_sync(0xffffffffu, m, 1));
        m = fmaxf(m, __shfl_xor_sync(0xffffffffu, m, 2));
        m = fmaxf(m, __shfl_xor_sync(0xffffffffu, m, 4));
        m = fmaxf(m, __shfl_xor_sync(0xffffffffu, m, 8));
        m = fmaxf(m, __shfl_xor_sync(0xffffffffu, m, 16));
        float s = QBF / fmaxf(m, EPSF);
        size_t base = (size_t)(r0 + r) * 64;
        xq[base + lane]      = pack_q4(a, s);
        xq[base + 32 + lane] = pack_q4(b, s);
        if (lane == 0) g_s1[r0 + r] = s;
    }
}

// ---------------------------------------------------------------------------
// Kernel 3: main GEMM pass. 128 tokens / block, 8 warps, 2 CTAs/SM.
// All global->smem via cp.async; no fp32 preprocessing.
// ---------------------------------------------------------------------------
__global__ __launch_bounds__(256, 2)
void bitnet_B(const float* __restrict__ prior, const float* __restrict__ b1,
              const float* __restrict__ b2, float* __restrict__ out) {
    extern __shared__ unsigned char sm[];
    const uint32_t sb = smem_u32(sm);
    const int tid   = threadIdx.x;
    const int lane  = tid & 31;
    const int w     = tid >> 5;
    const int g     = lane >> 2;   // mma group id (row)
    const int tg    = lane & 3;    // thread-in-group (col/k)
    const int token0 = blockIdx.x * 128;
    const int batch  = token0 >> 15;   // 32768 tokens per batch

    float* s1arr = (float*)(sm + OFF_S1);
    float* b1s   = (float*)(sm + OFF_B1);
    float* b2s   = (float*)(sm + OFF_B2);
    float* csum  = (float*)(sm + OFF_CS);

    // ---- async stage: XQ tile + weight tiles straight into padded smem ----
#pragma unroll
    for (int i = 0; i < 8; i++) {            // XQ: 2048 x 16B
        int c = tid + 256 * i;
        int row = c >> 4, k = c & 15;
        cp16(sb + OFF_XQ + row * XQ_STR + k * 16,
             g_XQ + (size_t)(token0 + row) * 256 + k * 16);
    }
#pragma unroll
    for (int i = 0; i < 8; i++) {            // W1: 2048 x 16B
        int c = tid + 256 * i;
        int o = c >> 4, k = c & 15;
        cp16(sb + OFF_W1 + o * W1_STR + k * 16, g_W1q + c * 16);
    }
#pragma unroll
    for (int i = 0; i < 4; i++) {            // W2: 1024 x 16B
        int c = tid + 256 * i;
        int o = c >> 3, k = c & 7;
        cp16(sb + OFF_W2 + o * W2_STR + k * 16, g_W2q + c * 16);
    }
    asm volatile("cp.async.commit_group;");

    if (tid < 128) {
        csum[tid]  = 0.0f;
        s1arr[tid] = __ldg(&g_s1[token0 + tid]);
        b1s[tid]   = __ldg(&b1[tid]);
        b2s[tid]   = __ldg(&b2[tid]);
    }
    asm volatile("cp.async.wait_group 0;" ::: "memory");
    __syncthreads();

    // ---- GEMM1: [16 x 256] x [256 x 128] per warp, int8 exact ----
    const int mb = w * 16;
    int acc[16][4];
#pragma unroll
    for (int n = 0; n < 16; n++) { acc[n][0] = acc[n][1] = acc[n][2] = acc[n][3] = 0; }

#pragma unroll
    for (int k8 = 0; k8 < 8; k8++) {
        const int kb = k8 * 32;
        unsigned a0 = *(const unsigned*)(sm + OFF_XQ + (mb + g)     * XQ_STR + kb + tg * 4);
        unsigned a1 = *(const unsigned*)(sm + OFF_XQ + (mb + g + 8) * XQ_STR + kb + tg * 4);
        unsigned a2 = *(const unsigned*)(sm + OFF_XQ + (mb + g)     * XQ_STR + kb + 16 + tg * 4);
        unsigned a3 = *(const unsigned*)(sm + OFF_XQ + (mb + g + 8) * XQ_STR + kb + 16 + tg * 4);
#pragma unroll
        for (int n = 0; n < 16; n++) {
            unsigned bb0 = *(const unsigned*)(sm + OFF_W1 + (n * 8 + g) * W1_STR + kb + tg * 4);
            unsigned bb1 = *(const unsigned*)(sm + OFF_W1 + (n * 8 + g) * W1_STR + kb + 16 + tg * 4);
            mma_s8(acc[n], a0, a1, a2, a3, bb0, bb1);
        }
    }

    // ---- Epilogue 1: dequant + bias + ReLU, per-row absmax, requantize ----
    const float wsc1 = g_wsc[0];
    const float dq0 = wsc1 / s1arr[mb + g];
    const float dq1 = wsc1 / s1arr[mb + g + 8];
    float hm0 = 0.0f, hm1 = 0.0f;
#pragma unroll
    for (int n = 0; n < 16; n++) {
        const int col = n * 8 + tg * 2;
        float c0 = fmaxf(0.0f, (float)acc[n][0] * dq0 + b1s[col]);
        float c1 = fmaxf(0.0f, (float)acc[n][1] * dq0 + b1s[col + 1]);
        float c2 = fmaxf(0.0f, (float)acc[n][2] * dq1 + b1s[col]);
        float c3 = fmaxf(0.0f, (float)acc[n][3] * dq1 + b1s[col + 1]);
        hm0 = fmaxf(hm0, fmaxf(c0, c1));
        hm1 = fmaxf(hm1, fmaxf(c2, c3));
        acc[n][0] = __float_as_int(c0);  // reuse accumulators as fp32 h storage
        acc[n][1] = __float_as_int(c1);
        acc[n][2] = __float_as_int(c2);
        acc[n][3] = __float_as_int(c3);
    }
    hm0 = fmaxf(hm0, __shfl_xor_sync(0xffffffffu, hm0, 1));
    hm0 = fmaxf(hm0, __shfl_xor_sync(0xffffffffu, hm0, 2));
    hm1 = fmaxf(hm1, __shfl_xor_sync(0xffffffffu, hm1, 1));
    hm1 = fmaxf(hm1, __shfl_xor_sync(0xffffffffu, hm1, 2));
    const float s2_0 = QBF / fmaxf(hm0, EPSF);
    const float s2_1 = QBF / fmaxf(hm1, EPSF);

    // HQ aliases the (now dead) XQ band of this warp: rows mb..mb+15, stride 272.
    __syncwarp();
#pragma unroll
    for (int n = 0; n < 16; n++) {
        int q0 = clamp_q(__float2int_rn(__int_as_float(acc[n][0]) * s2_0));
        int q1 = clamp_q(__float2int_rn(__int_as_float(acc[n][1]) * s2_0));
        int q2 = clamp_q(__float2int_rn(__int_as_float(acc[n][2]) * s2_1));
        int q3 = clamp_q(__float2int_rn(__int_as_float(acc[n][3]) * s2_1));
        unsigned short p0 = (unsigned short)((q0 & 255) | ((q1 & 255) << 8));
        unsigned short p1 = (unsigned short)((q2 & 255) | ((q3 & 255) << 8));
        *(unsigned short*)(sm + OFF_XQ + (mb + g)     * XQ_STR + n * 8 + tg * 2) = p0;
        *(unsigned short*)(sm + OFF_XQ + (mb + g + 8) * XQ_STR + n * 8 + tg * 2) = p1;
    }
    __syncwarp();

    // ---- GEMM2: [16 x 128] x [128 x 128] per warp ----
#pragma unroll
    for (int n = 0; n < 16; n++) { acc[n][0] = acc[n][1] = acc[n][2] = acc[n][3] = 0; }
#pragma unroll
    for (int k4 = 0; k4 < 4; k4++) {
        const int kb = k4 * 32;
        unsigned a0 = *(const unsigned*)(sm + OFF_XQ + (mb + g)     * XQ_STR + kb + tg * 4);
        unsigned a1 = *(const unsigned*)(sm + OFF_XQ + (mb + g + 8) * XQ_STR + kb + tg * 4);
        unsigned a2 = *(const unsigned*)(sm + OFF_XQ + (mb + g)     * XQ_STR + kb + 16 + tg * 4);
        unsigned a3 = *(const unsigned*)(sm + OFF_XQ + (mb + g + 8) * XQ_STR + kb + 16 + tg * 4);
#pragma unroll
        for (int n = 0; n < 16; n++) {
            unsigned bb0 = *(const unsigned*)(sm + OFF_W2 + (n * 8 + g) * W2_STR + kb + tg * 4);
            unsigned bb1 = *(const unsigned*)(sm + OFF_W2 + (n * 8 + g) * W2_STR + kb + 16 + tg * 4);
            mma_s8(acc[n], a0, a1, a2, a3, bb0, bb1);
        }
    }

    // ---- Epilogue 2: sigmoid, posterior_unnorm, store, column sums ----
    const float wsc2 = g_wsc[1];
    const float dq20 = wsc2 / s2_0;
    const float dq21 = wsc2 / s2_1;
    const size_t row0 = (size_t)(token0 + mb + g) * 128;
    const size_t row1 = row0 + (size_t)8 * 128;
    const float2* prior2 = (const float2*)prior;

#pragma unroll
    for (int n = 0; n < 16; n++) {
        const int col = n * 8 + tg * 2;
        float z0 = (float)acc[n][0] * dq20 + b2s[col];
        float z1 = (float)acc[n][1] * dq20 + b2s[col + 1];
        float z2 = (float)acc[n][2] * dq21 + b2s[col];
        float z3 = (float)acc[n][3] * dq21 + b2s[col + 1];
        float l0 = 1.0f / (1.0f + __expf(-z0));
        float l1 = 1.0f / (1.0f + __expf(-z1));
        float l2 = 1.0f / (1.0f + __expf(-z2));
        float l3 = 1.0f / (1.0f + __expf(-z3));
        float2 pr0 = __ldg(&prior2[(row0 + col) >> 1]);
        float2 pr1 = __ldg(&prior2[(row1 + col) >> 1]);
        float u0 = pr0.x * l0, u1 = pr0.y * l1;
        float u2 = pr1.x * l2, u3 = pr1.y * l3;
        *(float2*)(out + row0 + col) = make_float2(u0, u1);
        *(float2*)(out + row1 + col) = make_float2(u2, u3);
        float cs0 = u0 + u2, cs1 = u1 + u3;
        cs0 += __shfl_xor_sync(0xffffffffu, cs0, 4);
        cs0 += __shfl_xor_sync(0xffffffffu, cs0, 8);
        cs0 += __shfl_xor_sync(0xffffffffu, cs0, 16);
        cs1 += __shfl_xor_sync(0xffffffffu, cs1, 4);
        cs1 += __shfl_xor_sync(0xffffffffu, cs1, 8);
        cs1 += __shfl_xor_sync(0xffffffffu, cs1, 16);
        if (g == 0) {
            atomicAdd(&csum[col], cs0);
            atomicAdd(&csum[col + 1], cs1);
        }
    }
    __syncthreads();
    if (tid < 128) atomicAdd(&g_norm[batch * 128 + tid], (double)csum[tid]);
}

// ---------------------------------------------------------------------------
__global__ void finalize_norm() {
    int i = threadIdx.x;  // 1024 threads
    g_rnorm[i] = (float)(1.0 / fmax(g_norm[i], 1e-10));
}

// ---------------------------------------------------------------------------
__global__ void normalize_kernel(float4* __restrict__ out4) {
    int i = blockIdx.x * 256 + threadIdx.x;    // 8,388,608 float4s
    int b  = i >> 20;                          // 2^20 float4 per batch
    int f4 = i & 31;                           // 32 float4 per feature row
    float4 r = *(const float4*)&g_rnorm[b * 128 + f4 * 4];
    float4 v = out4[i];
    v.x *= r.x; v.y *= r.y; v.z *= r.z; v.w *= r.w;
    out4[i] = v;
}

// ---------------------------------------------------------------------------
extern "C" void kernel_launch(void* const* d_in, const int* in_sizes, int n_in,
                              void* d_out, int out_size) {
    const float* evid  = (const float*)d_in[0];
    const float* prior = (const float*)d_in[1];
    const float* W1    = (const float*)d_in[2];
    const float* b1    = (const float*)d_in[3];
    const float* W2    = (const float*)d_in[4];
    const float* b2    = (const float*)d_in[5];
    float* out = (float*)d_out;

    cudaFuncSetAttribute(bitnet_B, cudaFuncAttributeMaxDynamicSharedMemorySize,
                         SMEM_BYTES);

    quant_kernel<<<4096, 256>>>(evid, prior);
    prep_kernel<<<2, 1024>>>(W1, W2);
    bitnet_B<<<2048, 256, SMEM_BYTES>>>(prior, b1, b2, out);
    finalize_norm<<<1, 1024>>>();
    normalize_kernel<<<out_size / 1024, 256>>>((float4*)out);
}

// round 7
// speedup vs baseline: 1.0163x; 1.0163x over previous
#include <cuda_runtime.h>
#include <cstdint>
#include <math.h>

// ---------------------------------------------------------------------------
// SpatialBayesianLayer: BitLinear(2F->F) -> ReLU -> BitLinear(F->F) -> sigmoid
//                       -> posterior = prior*lik / sum_S(prior*lik)
// Exact-int8 tensor-core implementation (mma.sync m16n8k32.s8).
// R6: persistent bitnet_B (grid 296, 2 CTAs/SM): weights loaded once per CTA,
//     next-tile XQ prefetched via cp.async during epi1+GEMM2+epi2.
// ---------------------------------------------------------------------------

#define QBF 127.0f
#define EPSF 1e-5f

#define NTOK    262144          // 8 * 32768 tokens
#define NTILES  2048
#define GRIDP   296             // 2 x 148 persistent CTAs

// ---- device scratch (no runtime allocation allowed) ----
__device__ unsigned char g_XQ[NTOK * 256];   // quantized [prior|evidence] rows
__device__ float  g_s1[NTOK];                // per-token act scale (QB/absmax)
__device__ int8_t g_W1q[128 * 256];
__device__ int8_t g_W2q[128 * 128];
__device__ float  g_wsc[2];        // mean |w| per layer (ref's 1/ws)
__device__ double g_norm[1024];    // per (batch, feature) normalizer accumulators
__device__ float  g_rnorm[1024];   // reciprocal normalizers

// ---- shared memory layout for bitnet_B (bytes) ----
// XQ : 128 x 256 int8, stride 272 ((272/4)%32==4 -> conflict-free mma frags)
// W1 : 128 x 256 int8, stride 272
// W2 : 128 x 128 int8, stride 144
// HQ : 128 x 128 int8, stride 144 (separate so XQ can be prefetched)
#define OFF_XQ     0
#define XQ_STR     272
#define OFF_W1     34816
#define W1_STR     272
#define OFF_W2     69632
#define W2_STR     144
#define OFF_HQ     88064
#define HQ_STR     144
#define OFF_S1     106496      // double-buffered: 2 x 128 floats
#define OFF_B1     107520
#define OFF_B2     108032
#define OFF_CS     108544
#define SMEM_BYTES 109056

// ---------------------------------------------------------------------------
__device__ __forceinline__ void mma_s8(int* c,
                                       unsigned a0, unsigned a1, unsigned a2, unsigned a3,
                                       unsigned b0, unsigned b1) {
    asm volatile(
        "mma.sync.aligned.m16n8k32.row.col.s32.s8.s8.s32 "
        "{%0,%1,%2,%3}, {%4,%5,%6,%7}, {%8,%9}, {%0,%1,%2,%3};"
        : "+r"(c[0]), "+r"(c[1]), "+r"(c[2]), "+r"(c[3])
        : "r"(a0), "r"(a1), "r"(a2), "r"(a3), "r"(b0), "r"(b1));
}

__device__ __forceinline__ void cp16(uint32_t dst, const void* src) {
    asm volatile("cp.async.cg.shared.global [%0], [%1], 16;" :: "r"(dst), "l"(src));
}

__device__ __forceinline__ void cp4(uint32_t dst, const void* src) {
    asm volatile("cp.async.ca.shared.global [%0], [%1], 4;" :: "r"(dst), "l"(src));
}

__device__ __forceinline__ uint32_t smem_u32(const void* p) {
    uint32_t a;
    asm("{ .reg .u64 t; cvta.to.shared.u64 t, %1; cvt.u32.u64 %0, t; }"
        : "=r"(a) : "l"(p));
    return a;
}

__device__ __forceinline__ int clamp_q(int q) {
    return q < -128 ? -128 : (q > 127 ? 127 : q);
}

__device__ __forceinline__ unsigned pack_q4(float4 v, float s) {
    int q0 = clamp_q(__float2int_rn(v.x * s));
    int q1 = clamp_q(__float2int_rn(v.y * s));
    int q2 = clamp_q(__float2int_rn(v.z * s));
    int q3 = clamp_q(__float2int_rn(v.w * s));
    return (unsigned)(q0 & 255) | ((unsigned)(q1 & 255) << 8) |
           ((unsigned)(q2 & 255) << 16) | ((unsigned)(q3 & 255) << 24);
}

// ---------------------------------------------------------------------------
// Kernel 1: weight ternarization (absmean scale) + zero normalizers.
// ---------------------------------------------------------------------------
__global__ void prep_kernel(const float* __restrict__ W1,
                            const float* __restrict__ W2) {
    __shared__ double red[1024];
    __shared__ float s_ws;
    const int tid = threadIdx.x;
    const float* W = (blockIdx.x == 0) ? W1 : W2;
    int8_t* Wq     = (blockIdx.x == 0) ? g_W1q : g_W2q;
    const int n    = (blockIdx.x == 0) ? 128 * 256 : 128 * 128;

    if (tid < 512) g_norm[blockIdx.x * 512 + tid] = 0.0;

    double acc = 0.0;
    for (int i = tid; i < n; i += 1024) acc += (double)fabsf(W[i]);
    red[tid] = acc;
    __syncthreads();
    for (int s = 512; s > 0; s >>= 1) {
        if (tid < s) red[tid] += red[tid + s];
        __syncthreads();
    }
    if (tid == 0) {
        float m  = fmaxf((float)(red[0] / (double)n), EPSF);
        s_ws = 1.0f / m;                 // ref: ws = 1/clip(mean)
        g_wsc[blockIdx.x] = m;           // ref's t/ws (t = +-1) -> t*m
    }
    __syncthreads();
    const float ws = s_ws;
    for (int i = tid; i < n; i += 1024) {
        float t = rintf(W[i] * ws);      // round half-to-even like jnp.round
        t = fminf(1.0f, fmaxf(-1.0f, t));
        Wq[i] = (int8_t)t;
    }
}

// ---------------------------------------------------------------------------
// Kernel 2: streaming activation quantization. 1 warp per token row,
// 8 rows per warp, all loads front-batched (MLP=16).
// ---------------------------------------------------------------------------
__global__ __launch_bounds__(256)
void quant_kernel(const float* __restrict__ evid, const float* __restrict__ prior) {
    const int lane = threadIdx.x & 31;
    const int w    = threadIdx.x >> 5;
    const int r0   = blockIdx.x * 64 + w * 8;   // 4096 blocks * 8 warps * 8 rows

    const float4* pr4 = (const float4*)prior;
    const float4* ev4 = (const float4*)evid;
    unsigned* xq = (unsigned*)g_XQ;

    float4 pa[8], ea[8];
#pragma unroll
    for (int r = 0; r < 8; r++) {
        pa[r] = __ldg(&pr4[(size_t)(r0 + r) * 32 + lane]);
        ea[r] = __ldg(&ev4[(size_t)(r0 + r) * 32 + lane]);
    }
#pragma unroll
    for (int r = 0; r < 8; r++) {
        float4 a = pa[r], b = ea[r];
        float m = fmaxf(fmaxf(fabsf(a.x), fabsf(a.y)), fmaxf(fabsf(a.z), fabsf(a.w)));
        m = fmaxf(m, fmaxf(fmaxf(fabsf(b.x), fabsf(b.y)), fmaxf(fabsf(b.z), fabsf(b.w))));
        m = fmaxf(m, __shfl_xor_sync(0xffffffffu, m, 1));
        m = fmaxf(m, __shfl_xor_sync(0xffffffffu, m, 2));
        m = fmaxf(m, __shfl_xor_sync(0xffffffffu, m, 4));
        m = fmaxf(m, __shfl_xor_sync(0xffffffffu, m, 8));
        m = fmaxf(m, __shfl_xor_sync(0xffffffffu, m, 16));
        float s = QBF / fmaxf(m, EPSF);
        size_t base = (size_t)(r0 + r) * 64;
        xq[base + lane]      = pack_q4(a, s);
        xq[base + 32 + lane] = pack_q4(b, s);
        if (lane == 0) g_s1[r0 + r] = s;
    }
}

// ---------------------------------------------------------------------------
// Kernel 3: persistent main GEMM pass. 296 CTAs, ~7 tiles each, 2 CTAs/SM.
// Weights staged once; next tile's XQ prefetched during epi1+GEMM2+epi2.
// ---------------------------------------------------------------------------
__global__ __launch_bounds__(256, 2)
void bitnet_B(const float* __restrict__ prior, const float* __restrict__ b1,
              const float* __restrict__ b2, float* __restrict__ out) {
    extern __shared__ unsigned char sm[];
    const uint32_t sb = smem_u32(sm);
    const int tid   = threadIdx.x;
    const int lane  = tid & 31;
    const int w     = tid >> 5;
    const int g     = lane >> 2;   // mma group id (row)
    const int tg    = lane & 3;    // thread-in-group (col/k)
    const int mb    = w * 16;

    float* b1s  = (float*)(sm + OFF_B1);
    float* b2s  = (float*)(sm + OFF_B2);
    float* csum = (float*)(sm + OFF_CS);
    const float2* prior2 = (const float2*)prior;

    // ---- prologue: weights once + first tile XQ/scales ----
    int tile = blockIdx.x;
#pragma unroll
    for (int i = 0; i < 8; i++) {            // W1: 2048 x 16B
        int c = tid + 256 * i;
        int o = c >> 4, k = c & 15;
        cp16(sb + OFF_W1 + o * W1_STR + k * 16, g_W1q + c * 16);
    }
#pragma unroll
    for (int i = 0; i < 4; i++) {            // W2: 1024 x 16B
        int c = tid + 256 * i;
        int o = c >> 3, k = c & 7;
        cp16(sb + OFF_W2 + o * W2_STR + k * 16, g_W2q + c * 16);
    }
#pragma unroll
    for (int i = 0; i < 8; i++) {            // XQ tile 0: 2048 x 16B
        int c = tid + 256 * i;
        int row = c >> 4, k = c & 15;
        cp16(sb + OFF_XQ + row * XQ_STR + k * 16,
             g_XQ + (size_t)(tile * 128 + row) * 256 + k * 16);
    }
    if (tid < 128) {
        cp4(sb + OFF_S1 + tid * 4, g_s1 + tile * 128 + tid);
        csum[tid] = 0.0f;
        b1s[tid]  = __ldg(&b1[tid]);
        b2s[tid]  = __ldg(&b2[tid]);
    }
    asm volatile("cp.async.commit_group;");
    asm volatile("cp.async.wait_group 0;" ::: "memory");
    __syncthreads();

    const float wsc1 = g_wsc[0];
    const float wsc2 = g_wsc[1];
    int sbuf = 0;

    for (; tile < NTILES; ) {
        const int next   = tile + GRIDP;
        const int token0 = tile * 128;
        const int batch  = token0 >> 15;
        float* s1arr = (float*)(sm + OFF_S1 + sbuf * 512);

        // ---- GEMM1: [16 x 256] x [256 x 128] per warp, int8 exact ----
        int acc[16][4];
#pragma unroll
        for (int n = 0; n < 16; n++) { acc[n][0] = acc[n][1] = acc[n][2] = acc[n][3] = 0; }
#pragma unroll
        for (int k8 = 0; k8 < 8; k8++) {
            const int kb = k8 * 32;
            unsigned a0 = *(const unsigned*)(sm + OFF_XQ + (mb + g)     * XQ_STR + kb + tg * 4);
            unsigned a1 = *(const unsigned*)(sm + OFF_XQ + (mb + g + 8) * XQ_STR + kb + tg * 4);
            unsigned a2 = *(const unsigned*)(sm + OFF_XQ + (mb + g)     * XQ_STR + kb + 16 + tg * 4);
            unsigned a3 = *(const unsigned*)(sm + OFF_XQ + (mb + g + 8) * XQ_STR + kb + 16 + tg * 4);
#pragma unroll
            for (int n = 0; n < 16; n++) {
                unsigned bb0 = *(const unsigned*)(sm + OFF_W1 + (n * 8 + g) * W1_STR + kb + tg * 4);
                unsigned bb1 = *(const unsigned*)(sm + OFF_W1 + (n * 8 + g) * W1_STR + kb + 16 + tg * 4);
                mma_s8(acc[n], a0, a1, a2, a3, bb0, bb1);
            }
        }
        __syncthreads();   // all warps done reading XQ -> buffer reusable

        // ---- prefetch next tile's XQ + scales (overlaps epi1+GEMM2+epi2) ----
        if (next < NTILES) {
#pragma unroll
            for (int i = 0; i < 8; i++) {
                int c = tid + 256 * i;
                int row = c >> 4, k = c & 15;
                cp16(sb + OFF_XQ + row * XQ_STR + k * 16,
                     g_XQ + (size_t)(next * 128 + row) * 256 + k * 16);
            }
            if (tid < 128)
                cp4(sb + OFF_S1 + (sbuf ^ 1) * 512 + tid * 4, g_s1 + next * 128 + tid);
            asm volatile("cp.async.commit_group;");
        }

        // ---- Epilogue 1: dequant + bias + ReLU, quad absmax, requantize ----
        const float dq0 = wsc1 / s1arr[mb + g];
        const float dq1 = wsc1 / s1arr[mb + g + 8];
        float hm0 = 0.0f, hm1 = 0.0f;
#pragma unroll
        for (int n = 0; n < 16; n++) {
            const int col = n * 8 + tg * 2;
            float c0 = fmaxf(0.0f, (float)acc[n][0] * dq0 + b1s[col]);
            float c1 = fmaxf(0.0f, (float)acc[n][1] * dq0 + b1s[col + 1]);
            float c2 = fmaxf(0.0f, (float)acc[n][2] * dq1 + b1s[col]);
            float c3 = fmaxf(0.0f, (float)acc[n][3] * dq1 + b1s[col + 1]);
            hm0 = fmaxf(hm0, fmaxf(c0, c1));
            hm1 = fmaxf(hm1, fmaxf(c2, c3));
            acc[n][0] = __float_as_int(c0);
            acc[n][1] = __float_as_int(c1);
            acc[n][2] = __float_as_int(c2);
            acc[n][3] = __float_as_int(c3);
        }
        hm0 = fmaxf(hm0, __shfl_xor_sync(0xffffffffu, hm0, 1));
        hm0 = fmaxf(hm0, __shfl_xor_sync(0xffffffffu, hm0, 2));
        hm1 = fmaxf(hm1, __shfl_xor_sync(0xffffffffu, hm1, 1));
        hm1 = fmaxf(hm1, __shfl_xor_sync(0xffffffffu, hm1, 2));
        const float s2_0 = QBF / fmaxf(hm0, EPSF);
        const float s2_1 = QBF / fmaxf(hm1, EPSF);

#pragma unroll
        for (int n = 0; n < 16; n++) {
            int q0 = clamp_q(__float2int_rn(__int_as_float(acc[n][0]) * s2_0));
            int q1 = clamp_q(__float2int_rn(__int_as_float(acc[n][1]) * s2_0));
            int q2 = clamp_q(__float2int_rn(__int_as_float(acc[n][2]) * s2_1));
            int q3 = clamp_q(__float2int_rn(__int_as_float(acc[n][3]) * s2_1));
            unsigned short p0 = (unsigned short)((q0 & 255) | ((q1 & 255) << 8));
            unsigned short p1 = (unsigned short)((q2 & 255) | ((q3 & 255) << 8));
            *(unsigned short*)(sm + OFF_HQ + (mb + g)     * HQ_STR + n * 8 + tg * 2) = p0;
            *(unsigned short*)(sm + OFF_HQ + (mb + g + 8) * HQ_STR + n * 8 + tg * 2) = p1;
        }
        __syncwarp();   // each warp reads only its own 16 HQ rows

        // ---- GEMM2: [16 x 128] x [128 x 128] per warp ----
#pragma unroll
        for (int n = 0; n < 16; n++) { acc[n][0] = acc[n][1] = acc[n][2] = acc[n][3] = 0; }
#pragma unroll
        for (int k4 = 0; k4 < 4; k4++) {
            const int kb = k4 * 32;
            unsigned a0 = *(const unsigned*)(sm + OFF_HQ + (mb + g)     * HQ_STR + kb + tg * 4);
            unsigned a1 = *(const unsigned*)(sm + OFF_HQ + (mb + g + 8) * HQ_STR + kb + tg * 4);
            unsigned a2 = *(const unsigned*)(sm + OFF_HQ + (mb + g)     * HQ_STR + kb + 16 + tg * 4);
            unsigned a3 = *(const unsigned*)(sm + OFF_HQ + (mb + g + 8) * HQ_STR + kb + 16 + tg * 4);
#pragma unroll
            for (int n = 0; n < 16; n++) {
                unsigned bb0 = *(const unsigned*)(sm + OFF_W2 + (n * 8 + g) * W2_STR + kb + tg * 4);
                unsigned bb1 = *(const unsigned*)(sm + OFF_W2 + (n * 8 + g) * W2_STR + kb + 16 + tg * 4);
                mma_s8(acc[n], a0, a1, a2, a3, bb0, bb1);
            }
        }

        // ---- Epilogue 2: sigmoid, posterior_unnorm, store, column sums ----
        const float dq20 = wsc2 / s2_0;
        const float dq21 = wsc2 / s2_1;
        const size_t row0 = (size_t)(token0 + mb + g) * 128;
        const size_t row1 = row0 + (size_t)8 * 128;

#pragma unroll
        for (int n = 0; n < 16; n++) {
            const int col = n * 8 + tg * 2;
            float z0 = (float)acc[n][0] * dq20 + b2s[col];
            float z1 = (float)acc[n][1] * dq20 + b2s[col + 1];
            float z2 = (float)acc[n][2] * dq21 + b2s[col];
            float z3 = (float)acc[n][3] * dq21 + b2s[col + 1];
            float l0 = 1.0f / (1.0f + __expf(-z0));
            float l1 = 1.0f / (1.0f + __expf(-z1));
            float l2 = 1.0f / (1.0f + __expf(-z2));
            float l3 = 1.0f / (1.0f + __expf(-z3));
            float2 pr0 = __ldg(&prior2[(row0 + col) >> 1]);
            float2 pr1 = __ldg(&prior2[(row1 + col) >> 1]);
            float u0 = pr0.x * l0, u1 = pr0.y * l1;
            float u2 = pr1.x * l2, u3 = pr1.y * l3;
            *(float2*)(out + row0 + col) = make_float2(u0, u1);
            *(float2*)(out + row1 + col) = make_float2(u2, u3);
            float cs0 = u0 + u2, cs1 = u1 + u3;
            cs0 += __shfl_xor_sync(0xffffffffu, cs0, 4);
            cs0 += __shfl_xor_sync(0xffffffffu, cs0, 8);
            cs0 += __shfl_xor_sync(0xffffffffu, cs0, 16);
            cs1 += __shfl_xor_sync(0xffffffffu, cs1, 4);
            cs1 += __shfl_xor_sync(0xffffffffu, cs1, 8);
            cs1 += __shfl_xor_sync(0xffffffffu, cs1, 16);
            if (g == 0) {
                atomicAdd(&csum[col], cs0);
                atomicAdd(&csum[col + 1], cs1);
            }
        }
        __syncthreads();
        if (tid < 128) {
            atomicAdd(&g_norm[batch * 128 + tid], (double)csum[tid]);
            csum[tid] = 0.0f;
        }
        // wait for prefetched XQ + make csum reset visible
        asm volatile("cp.async.wait_group 0;" ::: "memory");
        __syncthreads();
        sbuf ^= 1;
        tile = next;
    }
}

// ---------------------------------------------------------------------------
__global__ void finalize_norm() {
    int i = threadIdx.x;  // 1024 threads
    g_rnorm[i] = 1.0f / fmaxf((float)g_norm[i], 1e-10f);
}

// ---------------------------------------------------------------------------
__global__ void normalize_kernel(float4* __restrict__ out4) {
    int i = blockIdx.x * 256 + threadIdx.x;    // 8,388,608 float4s
    int b  = i >> 20;                          // 2^20 float4 per batch
    int f4 = i & 31;                           // 32 float4 per feature row
    float4 r = *(const float4*)&g_rnorm[b * 128 + f4 * 4];
    float4 v = out4[i];
    v.x *= r.x; v.y *= r.y; v.z *= r.z; v.w *= r.w;
    out4[i] = v;
}

// ---------------------------------------------------------------------------
extern "C" void kernel_launch(void* const* d_in, const int* in_sizes, int n_in,
                              void* d_out, int out_size) {
    const float* evid  = (const float*)d_in[0];
    const float* prior = (const float*)d_in[1];
    const float* W1    = (const float*)d_in[2];
    const float* b1    = (const float*)d_in[3];
    const float* W2    = (const float*)d_in[4];
    const float* b2    = (const float*)d_in[5];
    float* out = (float*)d_out;

    cudaFuncSetAttribute(bitnet_B, cudaFuncAttributeMaxDynamicSharedMemorySize,
                         SMEM_BYTES);

    quant_kernel<<<4096, 256>>>(evid, prior);
    prep_kernel<<<2, 1024>>>(W1, W2);
    bitnet_B<<<GRIDP, 256, SMEM_BYTES>>>(prior, b1, b2, out);
    finalize_norm<<<1, 1024>>>();
    normalize_kernel<<<out_size / 1024, 256>>>((float4*)out);
}

// round 8
// speedup vs baseline: 1.1660x; 1.1473x over previous
#include <cuda_runtime.h>
#include <cstdint>
#include <math.h>

// ---------------------------------------------------------------------------
// SpatialBayesianLayer: BitLinear(2F->F) -> ReLU -> BitLinear(F->F) -> sigmoid
//                       -> posterior = prior*lik / sum_S(prior*lik)
// Exact-int8 tensor-core implementation (mma.sync m16n8k32.s8).
// R7: instruction-count attack. Magic-number round/pack (no F2I/I2F/clamps),
//     PRMT byte packing, ex2-folded sigmoid, fast divide.
// ---------------------------------------------------------------------------

#define QBF 127.0f
#define EPSF 1e-5f
#define MAGF 12582912.0f          // 1.5 * 2^23
#define MAG_I 0x4B400000          // bits of MAGF
#define L2E 1.4426950408889634f

#define NTOK    262144            // 8 * 32768 tokens
#define NTILES  2048
#define GRIDP   296               // 2 x 148 persistent CTAs

// ---- device scratch (no runtime allocation allowed) ----
__device__ unsigned char g_XQ[NTOK * 256];   // quantized [prior|evidence] rows
__device__ float  g_s1[NTOK];                // per-token act scale (QB/absmax)
__device__ int8_t g_W1q[128 * 256];
__device__ int8_t g_W2q[128 * 128];
__device__ float  g_wsc[2];        // mean |w| per layer (ref's 1/ws)
__device__ double g_norm[1024];    // per (batch, feature) normalizer accumulators
__device__ float  g_rnorm[1024];   // reciprocal normalizers

// ---- shared memory layout for bitnet_B (bytes) ----
#define OFF_XQ     0
#define XQ_STR     272
#define OFF_W1     34816
#define W1_STR     272
#define OFF_W2     69632
#define W2_STR     144
#define OFF_HQ     88064
#define HQ_STR     144
#define OFF_S1     106496      // double-buffered: 2 x 128 floats
#define OFF_B1     107520
#define OFF_B2L    108032      // -b2 * log2(e)
#define OFF_CS     108544
#define SMEM_BYTES 109056

// ---------------------------------------------------------------------------
__device__ __forceinline__ void mma_s8(int* c,
                                       unsigned a0, unsigned a1, unsigned a2, unsigned a3,
                                       unsigned b0, unsigned b1) {
    asm volatile(
        "mma.sync.aligned.m16n8k32.row.col.s32.s8.s8.s32 "
        "{%0,%1,%2,%3}, {%4,%5,%6,%7}, {%8,%9}, {%0,%1,%2,%3};"
        : "+r"(c[0]), "+r"(c[1]), "+r"(c[2]), "+r"(c[3])
        : "r"(a0), "r"(a1), "r"(a2), "r"(a3), "r"(b0), "r"(b1));
}

__device__ __forceinline__ void cp16(uint32_t dst, const void* src) {
    asm volatile("cp.async.cg.shared.global [%0], [%1], 16;" :: "r"(dst), "l"(src));
}

__device__ __forceinline__ void cp4(uint32_t dst, const void* src) {
    asm volatile("cp.async.ca.shared.global [%0], [%1], 4;" :: "r"(dst), "l"(src));
}

__device__ __forceinline__ uint32_t smem_u32(const void* p) {
    uint32_t a;
    asm("{ .reg .u64 t; cvta.to.shared.u64 t, %1; cvt.u32.u64 %0, t; }"
        : "=r"(a) : "l"(p));
    return a;
}

__device__ __forceinline__ float ex2f(float x) {
    float r;
    asm("ex2.approx.f32 %0, %1;" : "=f"(r) : "f"(x));
    return r;
}

// round(v.i * s) for |v*s| <= 127, bit-exact vs rintf(__fmul_rn(v,s)):
// FADD at 2^23 rounds half-to-even; low byte of the float bits IS the int8
// (two's complement falls out of integer borrow on the mantissa).
__device__ __forceinline__ unsigned pack_magic4(float4 v, float s) {
    unsigned b0 = __float_as_uint(__fadd_rn(__fmul_rn(v.x, s), MAGF));
    unsigned b1 = __float_as_uint(__fadd_rn(__fmul_rn(v.y, s), MAGF));
    unsigned b2 = __float_as_uint(__fadd_rn(__fmul_rn(v.z, s), MAGF));
    unsigned b3 = __float_as_uint(__fadd_rn(__fmul_rn(v.w, s), MAGF));
    unsigned r01 = __byte_perm(b0, b1, 0x0040);
    unsigned r23 = __byte_perm(b2, b3, 0x0040);
    return __byte_perm(r01, r23, 0x5410);
}

// exact int->float for |q| < 2^22 without I2F
__device__ __forceinline__ float i2f_magic(int q) {
    return __int_as_float(q + MAG_I) - MAGF;
}

// ---------------------------------------------------------------------------
// Kernel 1: weight ternarization (absmean scale) + zero normalizers.
// ---------------------------------------------------------------------------
__global__ void prep_kernel(const float* __restrict__ W1,
                            const float* __restrict__ W2) {
    __shared__ double red[1024];
    __shared__ float s_ws;
    const int tid = threadIdx.x;
    const float* W = (blockIdx.x == 0) ? W1 : W2;
    int8_t* Wq     = (blockIdx.x == 0) ? g_W1q : g_W2q;
    const int n    = (blockIdx.x == 0) ? 128 * 256 : 128 * 128;

    if (tid < 512) g_norm[blockIdx.x * 512 + tid] = 0.0;

    double acc = 0.0;
    for (int i = tid; i < n; i += 1024) acc += (double)fabsf(W[i]);
    red[tid] = acc;
    __syncthreads();
    for (int s = 512; s > 0; s >>= 1) {
        if (tid < s) red[tid] += red[tid + s];
        __syncthreads();
    }
    if (tid == 0) {
        float m  = fmaxf((float)(red[0] / (double)n), EPSF);
        s_ws = 1.0f / m;                 // ref: ws = 1/clip(mean)
        g_wsc[blockIdx.x] = m;           // ref's t/ws (t = +-1) -> t*m
    }
    __syncthreads();
    const float ws = s_ws;
    for (int i = tid; i < n; i += 1024) {
        float t = rintf(W[i] * ws);      // round half-to-even like jnp.round
        t = fminf(1.0f, fmaxf(-1.0f, t));
        Wq[i] = (int8_t)t;
    }
}

// ---------------------------------------------------------------------------
// Kernel 2: streaming activation quantization (magic round, PRMT pack).
// ---------------------------------------------------------------------------
__global__ __launch_bounds__(256)
void quant_kernel(const float* __restrict__ evid, const float* __restrict__ prior) {
    const int lane = threadIdx.x & 31;
    const int w    = threadIdx.x >> 5;
    const int r0   = blockIdx.x * 64 + w * 8;   // 4096 blocks * 8 warps * 8 rows

    const float4* pr4 = (const float4*)prior;
    const float4* ev4 = (const float4*)evid;
    unsigned* xq = (unsigned*)g_XQ;

    float4 pa[8], ea[8];
#pragma unroll
    for (int r = 0; r < 8; r++) {
        pa[r] = __ldg(&pr4[(size_t)(r0 + r) * 32 + lane]);
        ea[r] = __ldg(&ev4[(size_t)(r0 + r) * 32 + lane]);
    }
#pragma unroll
    for (int r = 0; r < 8; r++) {
        float4 a = pa[r], b = ea[r];
        float m = fmaxf(fmaxf(fabsf(a.x), fabsf(a.y)), fmaxf(fabsf(a.z), fabsf(a.w)));
        m = fmaxf(m, fmaxf(fmaxf(fabsf(b.x), fabsf(b.y)), fmaxf(fabsf(b.z), fabsf(b.w))));
        m = fmaxf(m, __shfl_xor_sync(0xffffffffu, m, 1));
        m = fmaxf(m, __shfl_xor_sync(0xffffffffu, m, 2));
        m = fmaxf(m, __shfl_xor_sync(0xffffffffu, m, 4));
        m = fmaxf(m, __shfl_xor_sync(0xffffffffu, m, 8));
        m = fmaxf(m, __shfl_xor_sync(0xffffffffu, m, 16));
        float s = QBF / fmaxf(m, EPSF);
        size_t base = (size_t)(r0 + r) * 64;
        xq[base + lane]      = pack_magic4(a, s);
        xq[base + 32 + lane] = pack_magic4(b, s);
        if (lane == 0) g_s1[r0 + r] = s;
    }
}

// ---------------------------------------------------------------------------
// Kernel 3: persistent main GEMM pass. 296 CTAs, ~7 tiles each, 2 CTAs/SM.
// ---------------------------------------------------------------------------
__global__ __launch_bounds__(256, 2)
void bitnet_B(const float* __restrict__ prior, const float* __restrict__ b1,
              const float* __restrict__ b2, float* __restrict__ out) {
    extern __shared__ unsigned char sm[];
    const uint32_t sb = smem_u32(sm);
    const int tid   = threadIdx.x;
    const int lane  = tid & 31;
    const int w     = tid >> 5;
    const int g     = lane >> 2;   // mma group id (row)
    const int tg    = lane & 3;    // thread-in-group (col/k)
    const int mb    = w * 16;

    float* b1s  = (float*)(sm + OFF_B1);
    float* b2l  = (float*)(sm + OFF_B2L);
    float* csum = (float*)(sm + OFF_CS);
    const float2* prior2 = (const float2*)prior;

    // ---- prologue: weights once + first tile XQ/scales ----
    int tile = blockIdx.x;
#pragma unroll
    for (int i = 0; i < 8; i++) {            // W1: 2048 x 16B
        int c = tid + 256 * i;
        int o = c >> 4, k = c & 15;
        cp16(sb + OFF_W1 + o * W1_STR + k * 16, g_W1q + c * 16);
    }
#pragma unroll
    for (int i = 0; i < 4; i++) {            // W2: 1024 x 16B
        int c = tid + 256 * i;
        int o = c >> 3, k = c & 7;
        cp16(sb + OFF_W2 + o * W2_STR + k * 16, g_W2q + c * 16);
    }
#pragma unroll
    for (int i = 0; i < 8; i++) {            // XQ tile 0: 2048 x 16B
        int c = tid + 256 * i;
        int row = c >> 4, k = c & 15;
        cp16(sb + OFF_XQ + row * XQ_STR + k * 16,
             g_XQ + (size_t)(tile * 128 + row) * 256 + k * 16);
    }
    if (tid < 128) {
        cp4(sb + OFF_S1 + tid * 4, g_s1 + tile * 128 + tid);
        csum[tid] = 0.0f;
        b1s[tid]  = __ldg(&b1[tid]);
        b2l[tid]  = -__ldg(&b2[tid]) * L2E;   // folded sigmoid bias
    }
    asm volatile("cp.async.commit_group;");
    asm volatile("cp.async.wait_group 0;" ::: "memory");
    __syncthreads();

    const float wsc1 = g_wsc[0];
    const float wsc2 = g_wsc[1];
    int sbuf = 0;

    for (; tile < NTILES; ) {
        const int next   = tile + GRIDP;
        const int token0 = tile * 128;
        const int batch  = token0 >> 15;
        float* s1arr = (float*)(sm + OFF_S1 + sbuf * 512);

        // ---- GEMM1: [16 x 256] x [256 x 128] per warp, int8 exact ----
        int acc[16][4];
#pragma unroll
        for (int n = 0; n < 16; n++) { acc[n][0] = acc[n][1] = acc[n][2] = acc[n][3] = 0; }
#pragma unroll
        for (int k8 = 0; k8 < 8; k8++) {
            const int kb = k8 * 32;
            unsigned a0 = *(const unsigned*)(sm + OFF_XQ + (mb + g)     * XQ_STR + kb + tg * 4);
            unsigned a1 = *(const unsigned*)(sm + OFF_XQ + (mb + g + 8) * XQ_STR + kb + tg * 4);
            unsigned a2 = *(const unsigned*)(sm + OFF_XQ + (mb + g)     * XQ_STR + kb + 16 + tg * 4);
            unsigned a3 = *(const unsigned*)(sm + OFF_XQ + (mb + g + 8) * XQ_STR + kb + 16 + tg * 4);
#pragma unroll
            for (int n = 0; n < 16; n++) {
                unsigned bb0 = *(const unsigned*)(sm + OFF_W1 + (n * 8 + g) * W1_STR + kb + tg * 4);
                unsigned bb1 = *(const unsigned*)(sm + OFF_W1 + (n * 8 + g) * W1_STR + kb + 16 + tg * 4);
                mma_s8(acc[n], a0, a1, a2, a3, bb0, bb1);
            }
        }
        __syncthreads();   // all warps done reading XQ -> buffer reusable

        // ---- prefetch next tile's XQ + scales (overlaps epi1+GEMM2+epi2) ----
        if (next < NTILES) {
#pragma unroll
            for (int i = 0; i < 8; i++) {
                int c = tid + 256 * i;
                int row = c >> 4, k = c & 15;
                cp16(sb + OFF_XQ + row * XQ_STR + k * 16,
                     g_XQ + (size_t)(next * 128 + row) * 256 + k * 16);
            }
            if (tid < 128)
                cp4(sb + OFF_S1 + (sbuf ^ 1) * 512 + tid * 4, g_s1 + next * 128 + tid);
            asm volatile("cp.async.commit_group;");
        }

        // ---- Epilogue 1: dequant + bias + ReLU, quad absmax, magic requant ----
        const float dq0 = wsc1 / s1arr[mb + g];
        const float dq1 = wsc1 / s1arr[mb + g + 8];
        float hm0 = 0.0f, hm1 = 0.0f;
#pragma unroll
        for (int n = 0; n < 16; n++) {
            const int col = n * 8 + tg * 2;
            float c0 = fmaxf(0.0f, i2f_magic(acc[n][0]) * dq0 + b1s[col]);
            float c1 = fmaxf(0.0f, i2f_magic(acc[n][1]) * dq0 + b1s[col + 1]);
            float c2 = fmaxf(0.0f, i2f_magic(acc[n][2]) * dq1 + b1s[col]);
            float c3 = fmaxf(0.0f, i2f_magic(acc[n][3]) * dq1 + b1s[col + 1]);
            hm0 = fmaxf(hm0, fmaxf(c0, c1));
            hm1 = fmaxf(hm1, fmaxf(c2, c3));
            acc[n][0] = __float_as_int(c0);
            acc[n][1] = __float_as_int(c1);
            acc[n][2] = __float_as_int(c2);
            acc[n][3] = __float_as_int(c3);
        }
        hm0 = fmaxf(hm0, __shfl_xor_sync(0xffffffffu, hm0, 1));
        hm0 = fmaxf(hm0, __shfl_xor_sync(0xffffffffu, hm0, 2));
        hm1 = fmaxf(hm1, __shfl_xor_sync(0xffffffffu, hm1, 1));
        hm1 = fmaxf(hm1, __shfl_xor_sync(0xffffffffu, hm1, 2));
        const float s2_0 = QBF / fmaxf(hm0, EPSF);
        const float s2_1 = QBF / fmaxf(hm1, EPSF);

#pragma unroll
        for (int n = 0; n < 16; n++) {
            // h >= 0, h*s2 <= 127: magic round, low byte = int8, no clamps
            unsigned q0 = __float_as_uint(__fadd_rn(__fmul_rn(__int_as_float(acc[n][0]), s2_0), MAGF));
            unsigned q1 = __float_as_uint(__fadd_rn(__fmul_rn(__int_as_float(acc[n][1]), s2_0), MAGF));
            unsigned q2 = __float_as_uint(__fadd_rn(__fmul_rn(__int_as_float(acc[n][2]), s2_1), MAGF));
            unsigned q3 = __float_as_uint(__fadd_rn(__fmul_rn(__int_as_float(acc[n][3]), s2_1), MAGF));
            unsigned short p0 = (unsigned short)__byte_perm(q0, q1, 0x0040);
            unsigned short p1 = (unsigned short)__byte_perm(q2, q3, 0x0040);
            *(unsigned short*)(sm + OFF_HQ + (mb + g)     * HQ_STR + n * 8 + tg * 2) = p0;
            *(unsigned short*)(sm + OFF_HQ + (mb + g + 8) * HQ_STR + n * 8 + tg * 2) = p1;
        }
        __syncwarp();   // each warp reads only its own 16 HQ rows

        // ---- GEMM2: [16 x 128] x [128 x 128] per warp ----
#pragma unroll
        for (int n = 0; n < 16; n++) { acc[n][0] = acc[n][1] = acc[n][2] = acc[n][3] = 0; }
#pragma unroll
        for (int k4 = 0; k4 < 4; k4++) {
            const int kb = k4 * 32;
            unsigned a0 = *(const unsigned*)(sm + OFF_HQ + (mb + g)     * HQ_STR + kb + tg * 4);
            unsigned a1 = *(const unsigned*)(sm + OFF_HQ + (mb + g + 8) * HQ_STR + kb + tg * 4);
            unsigned a2 = *(const unsigned*)(sm + OFF_HQ + (mb + g)     * HQ_STR + kb + 16 + tg * 4);
            unsigned a3 = *(const unsigned*)(sm + OFF_HQ + (mb + g + 8) * HQ_STR + kb + 16 + tg * 4);
#pragma unroll
            for (int n = 0; n < 16; n++) {
                unsigned bb0 = *(const unsigned*)(sm + OFF_W2 + (n * 8 + g) * W2_STR + kb + tg * 4);
                unsigned bb1 = *(const unsigned*)(sm + OFF_W2 + (n * 8 + g) * W2_STR + kb + 16 + tg * 4);
                mma_s8(acc[n], a0, a1, a2, a3, bb0, bb1);
            }
        }

        // ---- Epilogue 2: folded sigmoid (ex2 + fast div), store, col sums ----
        const float dq20 = wsc2 / s2_0;
        const float dq21 = wsc2 / s2_1;
        const float dql0 = -dq20 * L2E;     // exp(-z) = 2^(acc*dql + b2l)
        const float dql1 = -dq21 * L2E;
        const size_t row0 = (size_t)(token0 + mb + g) * 128;
        const size_t row1 = row0 + (size_t)8 * 128;

#pragma unroll
        for (int n = 0; n < 16; n++) {
            const int col = n * 8 + tg * 2;
            float e0 = ex2f(i2f_magic(acc[n][0]) * dql0 + b2l[col]);
            float e1 = ex2f(i2f_magic(acc[n][1]) * dql0 + b2l[col + 1]);
            float e2 = ex2f(i2f_magic(acc[n][2]) * dql1 + b2l[col]);
            float e3 = ex2f(i2f_magic(acc[n][3]) * dql1 + b2l[col + 1]);
            float2 pr0 = __ldg(&prior2[(row0 + col) >> 1]);
            float2 pr1 = __ldg(&prior2[(row1 + col) >> 1]);
            float u0 = __fdividef(pr0.x, 1.0f + e0);
            float u1 = __fdividef(pr0.y, 1.0f + e1);
            float u2 = __fdividef(pr1.x, 1.0f + e2);
            float u3 = __fdividef(pr1.y, 1.0f + e3);
            *(float2*)(out + row0 + col) = make_float2(u0, u1);
            *(float2*)(out + row1 + col) = make_float2(u2, u3);
            float cs0 = u0 + u2, cs1 = u1 + u3;
            cs0 += __shfl_xor_sync(0xffffffffu, cs0, 4);
            cs0 += __shfl_xor_sync(0xffffffffu, cs0, 8);
            cs0 += __shfl_xor_sync(0xffffffffu, cs0, 16);
            cs1 += __shfl_xor_sync(0xffffffffu, cs1, 4);
            cs1 += __shfl_xor_sync(0xffffffffu, cs1, 8);
            cs1 += __shfl_xor_sync(0xffffffffu, cs1, 16);
            if (g == 0) {
                atomicAdd(&csum[col], cs0);
                atomicAdd(&csum[col + 1], cs1);
            }
        }
        __syncthreads();
        if (tid < 128) {
            atomicAdd(&g_norm[batch * 128 + tid], (double)csum[tid]);
            csum[tid] = 0.0f;
        }
        asm volatile("cp.async.wait_group 0;" ::: "memory");
        __syncthreads();
        sbuf ^= 1;
        tile = next;
    }
}

// ---------------------------------------------------------------------------
__global__ void finalize_norm() {
    int i = threadIdx.x;  // 1024 threads
    g_rnorm[i] = 1.0f / fmaxf((float)g_norm[i], 1e-10f);
}

// ---------------------------------------------------------------------------
__global__ void normalize_kernel(float4* __restrict__ out4) {
    int i = blockIdx.x * 256 + threadIdx.x;    // 8,388,608 float4s
    int b  = i >> 20;                          // 2^20 float4 per batch
    int f4 = i & 31;                           // 32 float4 per feature row
    float4 r = *(const float4*)&g_rnorm[b * 128 + f4 * 4];
    float4 v = out4[i];
    v.x *= r.x; v.y *= r.y; v.z *= r.z; v.w *= r.w;
    out4[i] = v;
}

// ---------------------------------------------------------------------------
extern "C" void kernel_launch(void* const* d_in, const int* in_sizes, int n_in,
                              void* d_out, int out_size) {
    const float* evid  = (const float*)d_in[0];
    const float* prior = (const float*)d_in[1];
    const float* W1    = (const float*)d_in[2];
    const float* b1    = (const float*)d_in[3];
    const float* W2    = (const float*)d_in[4];
    const float* b2    = (const float*)d_in[5];
    float* out = (float*)d_out;

    cudaFuncSetAttribute(bitnet_B, cudaFuncAttributeMaxDynamicSharedMemorySize,
                         SMEM_BYTES);

    quant_kernel<<<4096, 256>>>(evid, prior);
    prep_kernel<<<2, 1024>>>(W1, W2);
    bitnet_B<<<GRIDP, 256, SMEM_BYTES>>>(prior, b1, b2, out);
    finalize_norm<<<1, 1024>>>();
    normalize_kernel<<<out_size / 1024, 256>>>((float4*)out);
}

// round 9
// speedup vs baseline: 1.1948x; 1.0247x over previous
#include <cuda_runtime.h>
#include <cstdint>
#include <math.h>

// ---------------------------------------------------------------------------
// SpatialBayesianLayer: BitLinear(2F->F) -> ReLU -> BitLinear(F->F) -> sigmoid
//                       -> posterior = prior*lik / sum_S(prior*lik)
// Exact-int8 tensor-core implementation (mma.sync m16n8k32.s8).
// R8: ldmatrix (LDSM.x4) for all MMA fragments: ~4x fewer shared-mem issues
//     in both GEMMs. Magic round/pack + folded sigmoid retained from R7.
// ---------------------------------------------------------------------------

#define QBF 127.0f
#define EPSF 1e-5f
#define MAGF 12582912.0f          // 1.5 * 2^23
#define MAG_I 0x4B400000          // bits of MAGF
#define L2E 1.4426950408889634f

#define NTOK    262144            // 8 * 32768 tokens
#define NTILES  2048
#define GRIDP   296               // 2 x 148 persistent CTAs

// ---- device scratch (no runtime allocation allowed) ----
__device__ unsigned char g_XQ[NTOK * 256];   // quantized [prior|evidence] rows
__device__ float  g_s1[NTOK];                // per-token act scale (QB/absmax)
__device__ int8_t g_W1q[128 * 256];
__device__ int8_t g_W2q[128 * 128];
__device__ float  g_wsc[2];        // mean |w| per layer (ref's 1/ws)
__device__ double g_norm[1024];    // per (batch, feature) normalizer accumulators
__device__ float  g_rnorm[1024];   // reciprocal normalizers

// ---- shared memory layout for bitnet_B (bytes) ----
// strides 272 and 144 are both ==4 words mod 32 -> LDSM phases conflict-free
#define OFF_XQ     0
#define XQ_STR     272
#define OFF_W1     34816
#define W1_STR     272
#define OFF_W2     69632
#define W2_STR     144
#define OFF_HQ     88064
#define HQ_STR     144
#define OFF_S1     106496      // double-buffered: 2 x 128 floats
#define OFF_B1     107520
#define OFF_B2L    108032      // -b2 * log2(e)
#define OFF_CS     108544
#define SMEM_BYTES 109056

// ---------------------------------------------------------------------------
__device__ __forceinline__ void mma_s8(int* c,
                                       unsigned a0, unsigned a1, unsigned a2, unsigned a3,
                                       unsigned b0, unsigned b1) {
    asm volatile(
        "mma.sync.aligned.m16n8k32.row.col.s32.s8.s8.s32 "
        "{%0,%1,%2,%3}, {%4,%5,%6,%7}, {%8,%9}, {%0,%1,%2,%3};"
        : "+r"(c[0]), "+r"(c[1]), "+r"(c[2]), "+r"(c[3])
        : "r"(a0), "r"(a1), "r"(a2), "r"(a3), "r"(b0), "r"(b1));
}

__device__ __forceinline__ void ldsm4(unsigned& r0, unsigned& r1,
                                      unsigned& r2, unsigned& r3, uint32_t addr) {
    asm volatile("ldmatrix.sync.aligned.m8n8.x4.shared.b16 {%0,%1,%2,%3}, [%4];"
                 : "=r"(r0), "=r"(r1), "=r"(r2), "=r"(r3) : "r"(addr));
}

__device__ __forceinline__ void cp16(uint32_t dst, const void* src) {
    asm volatile("cp.async.cg.shared.global [%0], [%1], 16;" :: "r"(dst), "l"(src));
}

__device__ __forceinline__ void cp4(uint32_t dst, const void* src) {
    asm volatile("cp.async.ca.shared.global [%0], [%1], 4;" :: "r"(dst), "l"(src));
}

__device__ __forceinline__ uint32_t smem_u32(const void* p) {
    uint32_t a;
    asm("{ .reg .u64 t; cvta.to.shared.u64 t, %1; cvt.u32.u64 %0, t; }"
        : "=r"(a) : "l"(p));
    return a;
}

__device__ __forceinline__ float ex2f(float x) {
    float r;
    asm("ex2.approx.f32 %0, %1;" : "=f"(r) : "f"(x));
    return r;
}

// round(v.i * s) for |v*s| <= 127, bit-exact vs rintf: FADD at 1.5*2^23 rounds
// half-to-even; low byte of float bits IS the int8 (two's complement).
__device__ __forceinline__ unsigned pack_magic4(float4 v, float s) {
    unsigned b0 = __float_as_uint(__fadd_rn(__fmul_rn(v.x, s), MAGF));
    unsigned b1 = __float_as_uint(__fadd_rn(__fmul_rn(v.y, s), MAGF));
    unsigned b2 = __float_as_uint(__fadd_rn(__fmul_rn(v.z, s), MAGF));
    unsigned b3 = __float_as_uint(__fadd_rn(__fmul_rn(v.w, s), MAGF));
    unsigned r01 = __byte_perm(b0, b1, 0x0040);
    unsigned r23 = __byte_perm(b2, b3, 0x0040);
    return __byte_perm(r01, r23, 0x5410);
}

// exact int->float for |q| < 2^22 without I2F
__device__ __forceinline__ float i2f_magic(int q) {
    return __int_as_float(q + MAG_I) - MAGF;
}

// ---------------------------------------------------------------------------
// Kernel 1: weight ternarization (absmean scale) + zero normalizers.
// ---------------------------------------------------------------------------
__global__ void prep_kernel(const float* __restrict__ W1,
                            const float* __restrict__ W2) {
    __shared__ double red[1024];
    __shared__ float s_ws;
    const int tid = threadIdx.x;
    const float* W = (blockIdx.x == 0) ? W1 : W2;
    int8_t* Wq     = (blockIdx.x == 0) ? g_W1q : g_W2q;
    const int n    = (blockIdx.x == 0) ? 128 * 256 : 128 * 128;

    if (tid < 512) g_norm[blockIdx.x * 512 + tid] = 0.0;

    double acc = 0.0;
    for (int i = tid; i < n; i += 1024) acc += (double)fabsf(W[i]);
    red[tid] = acc;
    __syncthreads();
    for (int s = 512; s > 0; s >>= 1) {
        if (tid < s) red[tid] += red[tid + s];
        __syncthreads();
    }
    if (tid == 0) {
        float m  = fmaxf((float)(red[0] / (double)n), EPSF);
        s_ws = 1.0f / m;                 // ref: ws = 1/clip(mean)
        g_wsc[blockIdx.x] = m;           // ref's t/ws (t = +-1) -> t*m
    }
    __syncthreads();
    const float ws = s_ws;
    for (int i = tid; i < n; i += 1024) {
        float t = rintf(W[i] * ws);      // round half-to-even like jnp.round
        t = fminf(1.0f, fmaxf(-1.0f, t));
        Wq[i] = (int8_t)t;
    }
}

// ---------------------------------------------------------------------------
// Kernel 2: streaming activation quantization (magic round, PRMT pack).
// ---------------------------------------------------------------------------
__global__ __launch_bounds__(256)
void quant_kernel(const float* __restrict__ evid, const float* __restrict__ prior) {
    const int lane = threadIdx.x & 31;
    const int w    = threadIdx.x >> 5;
    const int r0   = blockIdx.x * 64 + w * 8;   // 4096 blocks * 8 warps * 8 rows

    const float4* pr4 = (const float4*)prior;
    const float4* ev4 = (const float4*)evid;
    unsigned* xq = (unsigned*)g_XQ;

    float4 pa[8], ea[8];
#pragma unroll
    for (int r = 0; r < 8; r++) {
        pa[r] = __ldg(&pr4[(size_t)(r0 + r) * 32 + lane]);
        ea[r] = __ldg(&ev4[(size_t)(r0 + r) * 32 + lane]);
    }
#pragma unroll
    for (int r = 0; r < 8; r++) {
        float4 a = pa[r], b = ea[r];
        float m = fmaxf(fmaxf(fabsf(a.x), fabsf(a.y)), fmaxf(fabsf(a.z), fabsf(a.w)));
        m = fmaxf(m, fmaxf(fmaxf(fabsf(b.x), fabsf(b.y)), fmaxf(fabsf(b.z), fabsf(b.w))));
        m = fmaxf(m, __shfl_xor_sync(0xffffffffu, m, 1));
        m = fmaxf(m, __shfl_xor_sync(0xffffffffu, m, 2));
        m = fmaxf(m, __shfl_xor_sync(0xffffffffu, m, 4));
        m = fmaxf(m, __shfl_xor_sync(0xffffffffu, m, 8));
        m = fmaxf(m, __shfl_xor_sync(0xffffffffu, m, 16));
        float s = QBF / fmaxf(m, EPSF);
        size_t base = (size_t)(r0 + r) * 64;
        xq[base + lane]      = pack_magic4(a, s);
        xq[base + 32 + lane] = pack_magic4(b, s);
        if (lane == 0) g_s1[r0 + r] = s;
    }
}

// ---------------------------------------------------------------------------
// Kernel 3: persistent main GEMM pass. 296 CTAs, ~7 tiles each, 2 CTAs/SM.
// ---------------------------------------------------------------------------
__global__ __launch_bounds__(256, 2)
void bitnet_B(const float* __restrict__ prior, const float* __restrict__ b1,
              const float* __restrict__ b2, float* __restrict__ out) {
    extern __shared__ unsigned char sm[];
    const uint32_t sb = smem_u32(sm);
    const int tid   = threadIdx.x;
    const int lane  = tid & 31;
    const int w     = tid >> 5;
    const int g     = lane >> 4 == 0 ? (lane >> 2) : (lane >> 2);  // lane/4
    const int tg    = lane & 3;
    const int mb    = w * 16;

    // ldmatrix per-lane address components
    const int lrow  = lane & 15;              // row within 16-row A group
    const int lkoff = (lane >> 4) * 16;       // 0 or 16 (k half)
    const int brow  = ((lane >> 4) & 1) * 8 + (lane & 7);  // row within 16-row B pair
    const int bkoff = ((lane >> 3) & 1) * 16;

    float* b1s  = (float*)(sm + OFF_B1);
    float* b2l  = (float*)(sm + OFF_B2L);
    float* csum = (float*)(sm + OFF_CS);
    const float2* prior2 = (const float2*)prior;

    // ---- prologue: weights once + first tile XQ/scales ----
    int tile = blockIdx.x;
#pragma unroll
    for (int i = 0; i < 8; i++) {            // W1: 2048 x 16B
        int c = tid + 256 * i;
        int o = c >> 4, k = c & 15;
        cp16(sb + OFF_W1 + o * W1_STR + k * 16, g_W1q + c * 16);
    }
#pragma unroll
    for (int i = 0; i < 4; i++) {            // W2: 1024 x 16B
        int c = tid + 256 * i;
        int o = c >> 3, k = c & 7;
        cp16(sb + OFF_W2 + o * W2_STR + k * 16, g_W2q + c * 16);
    }
#pragma unroll
    for (int i = 0; i < 8; i++) {            // XQ tile 0: 2048 x 16B
        int c = tid + 256 * i;
        int row = c >> 4, k = c & 15;
        cp16(sb + OFF_XQ + row * XQ_STR + k * 16,
             g_XQ + (size_t)(tile * 128 + row) * 256 + k * 16);
    }
    if (tid < 128) {
        cp4(sb + OFF_S1 + tid * 4, g_s1 + tile * 128 + tid);
        csum[tid] = 0.0f;
        b1s[tid]  = __ldg(&b1[tid]);
        b2l[tid]  = -__ldg(&b2[tid]) * L2E;   // folded sigmoid bias
    }
    asm volatile("cp.async.commit_group;");
    asm volatile("cp.async.wait_group 0;" ::: "memory");
    __syncthreads();

    const float wsc1 = g_wsc[0];
    const float wsc2 = g_wsc[1];
    int sbuf = 0;

    // per-lane LDSM base addresses (tile-invariant parts)
    const uint32_t aAbase = sb + OFF_XQ + (mb + lrow) * XQ_STR + lkoff;
    const uint32_t aHbase = sb + OFF_HQ + (mb + lrow) * HQ_STR + lkoff;
    const uint32_t bW1base = sb + OFF_W1 + brow * W1_STR + bkoff;
    const uint32_t bW2base = sb + OFF_W2 + brow * W2_STR + bkoff;

    for (; tile < NTILES; ) {
        const int next   = tile + GRIDP;
        const int token0 = tile * 128;
        const int batch  = token0 >> 15;
        float* s1arr = (float*)(sm + OFF_S1 + sbuf * 512);

        // ---- GEMM1: [16 x 256] x [256 x 128] per warp, int8 exact ----
        int acc[16][4];
#pragma unroll
        for (int n = 0; n < 16; n++) { acc[n][0] = acc[n][1] = acc[n][2] = acc[n][3] = 0; }
#pragma unroll
        for (int k8 = 0; k8 < 8; k8++) {
            const int kb = k8 * 32;
            unsigned a0, a1, a2, a3;
            ldsm4(a0, a1, a2, a3, aAbase + kb);
#pragma unroll
            for (int n2 = 0; n2 < 8; n2++) {
                unsigned b0, b1r, b2r, b3;   // bb0/bb1 for n=2*n2 and 2*n2+1
                ldsm4(b0, b1r, b2r, b3, bW1base + (n2 * 16) * W1_STR + kb);
                mma_s8(acc[n2 * 2],     a0, a1, a2, a3, b0,  b1r);
                mma_s8(acc[n2 * 2 + 1], a0, a1, a2, a3, b2r, b3);
            }
        }
        __syncthreads();   // all warps done reading XQ -> buffer reusable

        // ---- prefetch next tile's XQ + scales (overlaps epi1+GEMM2+epi2) ----
        if (next < NTILES) {
#pragma unroll
            for (int i = 0; i < 8; i++) {
                int c = tid + 256 * i;
                int row = c >> 4, k = c & 15;
                cp16(sb + OFF_XQ + row * XQ_STR + k * 16,
                     g_XQ + (size_t)(next * 128 + row) * 256 + k * 16);
            }
            if (tid < 128)
                cp4(sb + OFF_S1 + (sbuf ^ 1) * 512 + tid * 4, g_s1 + next * 128 + tid);
            asm volatile("cp.async.commit_group;");
        }

        // ---- Epilogue 1: dequant + bias + ReLU, quad absmax, magic requant ----
        const float dq0 = wsc1 / s1arr[mb + g];
        const float dq1 = wsc1 / s1arr[mb + g + 8];
        float hm0 = 0.0f, hm1 = 0.0f;
#pragma unroll
        for (int n = 0; n < 16; n++) {
            const int col = n * 8 + tg * 2;
            float c0 = fmaxf(0.0f, i2f_magic(acc[n][0]) * dq0 + b1s[col]);
            float c1 = fmaxf(0.0f, i2f_magic(acc[n][1]) * dq0 + b1s[col + 1]);
            float c2 = fmaxf(0.0f, i2f_magic(acc[n][2]) * dq1 + b1s[col]);
            float c3 = fmaxf(0.0f, i2f_magic(acc[n][3]) * dq1 + b1s[col + 1]);
            hm0 = fmaxf(hm0, fmaxf(c0, c1));
            hm1 = fmaxf(hm1, fmaxf(c2, c3));
            acc[n][0] = __float_as_int(c0);
            acc[n][1] = __float_as_int(c1);
            acc[n][2] = __float_as_int(c2);
            acc[n][3] = __float_as_int(c3);
        }
        hm0 = fmaxf(hm0, __shfl_xor_sync(0xffffffffu, hm0, 1));
        hm0 = fmaxf(hm0, __shfl_xor_sync(0xffffffffu, hm0, 2));
        hm1 = fmaxf(hm1, __shfl_xor_sync(0xffffffffu, hm1, 1));
        hm1 = fmaxf(hm1, __shfl_xor_sync(0xffffffffu, hm1, 2));
        const float s2_0 = QBF / fmaxf(hm0, EPSF);
        const float s2_1 = QBF / fmaxf(hm1, EPSF);

#pragma unroll
        for (int n = 0; n < 16; n++) {
            unsigned q0 = __float_as_uint(__fadd_rn(__fmul_rn(__int_as_float(acc[n][0]), s2_0), MAGF));
            unsigned q1 = __float_as_uint(__fadd_rn(__fmul_rn(__int_as_float(acc[n][1]), s2_0), MAGF));
            unsigned q2 = __float_as_uint(__fadd_rn(__fmul_rn(__int_as_float(acc[n][2]), s2_1), MAGF));
            unsigned q3 = __float_as_uint(__fadd_rn(__fmul_rn(__int_as_float(acc[n][3]), s2_1), MAGF));
            unsigned short p0 = (unsigned short)__byte_perm(q0, q1, 0x0040);
            unsigned short p1 = (unsigned short)__byte_perm(q2, q3, 0x0040);
            *(unsigned short*)(sm + OFF_HQ + (mb + g)     * HQ_STR + n * 8 + tg * 2) = p0;
            *(unsigned short*)(sm + OFF_HQ + (mb + g + 8) * HQ_STR + n * 8 + tg * 2) = p1;
        }
        __syncwarp();   // each warp reads only its own 16 HQ rows

        // ---- GEMM2: [16 x 128] x [128 x 128] per warp ----
#pragma unroll
        for (int n = 0; n < 16; n++) { acc[n][0] = acc[n][1] = acc[n][2] = acc[n][3] = 0; }
#pragma unroll
        for (int k4 = 0; k4 < 4; k4++) {
            const int kb = k4 * 32;
            unsigned a0, a1, a2, a3;
            ldsm4(a0, a1, a2, a3, aHbase + kb);
#pragma unroll
            for (int n2 = 0; n2 < 8; n2++) {
                unsigned b0, b1r, b2r, b3;
                ldsm4(b0, b1r, b2r, b3, bW2base + (n2 * 16) * W2_STR + kb);
                mma_s8(acc[n2 * 2],     a0, a1, a2, a3, b0,  b1r);
                mma_s8(acc[n2 * 2 + 1], a0, a1, a2, a3, b2r, b3);
            }
        }

        // ---- Epilogue 2: folded sigmoid (ex2 + fast div), store, col sums ----
        const float dq20 = wsc2 / s2_0;
        const float dq21 = wsc2 / s2_1;
        const float dql0 = -dq20 * L2E;     // exp(-z) = 2^(acc*dql + b2l)
        const float dql1 = -dq21 * L2E;
        const size_t row0 = (size_t)(token0 + mb + g) * 128;
        const size_t row1 = row0 + (size_t)8 * 128;

#pragma unroll
        for (int n = 0; n < 16; n++) {
            const int col = n * 8 + tg * 2;
            float e0 = ex2f(i2f_magic(acc[n][0]) * dql0 + b2l[col]);
            float e1 = ex2f(i2f_magic(acc[n][1]) * dql0 + b2l[col + 1]);
            float e2 = ex2f(i2f_magic(acc[n][2]) * dql1 + b2l[col]);
            float e3 = ex2f(i2f_magic(acc[n][3]) * dql1 + b2l[col + 1]);
            float2 pr0 = __ldg(&prior2[(row0 + col) >> 1]);
            float2 pr1 = __ldg(&prior2[(row1 + col) >> 1]);
            float u0 = __fdividef(pr0.x, 1.0f + e0);
            float u1 = __fdividef(pr0.y, 1.0f + e1);
            float u2 = __fdividef(pr1.x, 1.0f + e2);
            float u3 = __fdividef(pr1.y, 1.0f + e3);
            *(float2*)(out + row0 + col) = make_float2(u0, u1);
            *(float2*)(out + row1 + col) = make_float2(u2, u3);
            float cs0 = u0 + u2, cs1 = u1 + u3;
            cs0 += __shfl_xor_sync(0xffffffffu, cs0, 4);
            cs0 += __shfl_xor_sync(0xffffffffu, cs0, 8);
            cs0 += __shfl_xor_sync(0xffffffffu, cs0, 16);
            cs1 += __shfl_xor_sync(0xffffffffu, cs1, 4);
            cs1 += __shfl_xor_sync(0xffffffffu, cs1, 8);
            cs1 += __shfl_xor_sync(0xffffffffu, cs1, 16);
            if (g == 0) {
                atomicAdd(&csum[col], cs0);
                atomicAdd(&csum[col + 1], cs1);
            }
        }
        __syncthreads();
        if (tid < 128) {
            atomicAdd(&g_norm[batch * 128 + tid], (double)csum[tid]);
            csum[tid] = 0.0f;
        }
        asm volatile("cp.async.wait_group 0;" ::: "memory");
        __syncthreads();
        sbuf ^= 1;
        tile = next;
    }
}

// ---------------------------------------------------------------------------
__global__ void finalize_norm() {
    int i = threadIdx.x;  // 1024 threads
    g_rnorm[i] = 1.0f / fmaxf((float)g_norm[i], 1e-10f);
}

// ---------------------------------------------------------------------------
__global__ void normalize_kernel(float4* __restrict__ out4) {
    int i = blockIdx.x * 256 + threadIdx.x;    // 8,388,608 float4s
    int b  = i >> 20;                          // 2^20 float4 per batch
    int f4 = i & 31;                           // 32 float4 per feature row
    float4 r = *(const float4*)&g_rnorm[b * 128 + f4 * 4];
    float4 v = out4[i];
    v.x *= r.x; v.y *= r.y; v.z *= r.z; v.w *= r.w;
    out4[i] = v;
}

// ---------------------------------------------------------------------------
extern "C" void kernel_launch(void* const* d_in, const int* in_sizes, int n_in,
                              void* d_out, int out_size) {
    const float* evid  = (const float*)d_in[0];
    const float* prior = (const float*)d_in[1];
    const float* W1    = (const float*)d_in[2];
    const float* b1    = (const float*)d_in[3];
    const float* W2    = (const float*)d_in[4];
    const float* b2    = (const float*)d_in[5];
    float* out = (float*)d_out;

    cudaFuncSetAttribute(bitnet_B, cudaFuncAttributeMaxDynamicSharedMemorySize,
                         SMEM_BYTES);

    quant_kernel<<<4096, 256>>>(evid, prior);
    prep_kernel<<<2, 1024>>>(W1, W2);
    bitnet_B<<<GRIDP, 256, SMEM_BYTES>>>(prior, b1, b2, out);
    finalize_norm<<<1, 1024>>>();
    normalize_kernel<<<out_size / 1024, 256>>>((float4*)out);
}

// round 10
// speedup vs baseline: 1.2961x; 1.0848x over previous
#include <cuda_runtime.h>
#include <cstdint>
#include <math.h>

// ---------------------------------------------------------------------------
// SpatialBayesianLayer: BitLinear(2F->F) -> ReLU -> BitLinear(F->F) -> sigmoid
//                       -> posterior = prior*lik / sum_S(prior*lik)
// Exact-int8 tensor-core implementation (mma.sync m16n8k32.s8).
// R9: quantization fused back into the persistent GEMM kernel (warp-private
//     A-bands -> syncwarp only). DRAM traffic 940 -> ~670 MB.
// ---------------------------------------------------------------------------

#define QBF 127.0f
#define EPSF 1e-5f
#define MAGF 12582912.0f          // 1.5 * 2^23
#define MAG_I 0x4B400000          // bits of MAGF
#define L2E 1.4426950408889634f

#define NTILES  2048
#define GRIDP   296               // 2 x 148 persistent CTAs

// ---- device scratch (no runtime allocation allowed) ----
__device__ int8_t g_W1q[128 * 256];
__device__ int8_t g_W2q[128 * 128];
__device__ float  g_wsc[2];        // mean |w| per layer (ref's 1/ws)
__device__ double g_norm[1024];    // per (batch, feature) normalizer accumulators
__device__ float  g_rnorm[1024];   // reciprocal normalizers

// ---- shared memory layout for bitnet_F (bytes) ----
// strides 272 and 144 are both ==4 words mod 32 -> LDSM phases conflict-free
#define OFF_XQ     0
#define XQ_STR     272
#define OFF_W1     34816
#define W1_STR     272
#define OFF_W2     69632
#define W2_STR     144
#define OFF_HQ     88064
#define HQ_STR     144
#define OFF_S1     106496      // 128 floats (warp-private 16-row slices)
#define OFF_B1     107008
#define OFF_B2L    107520      // -b2 * log2(e)
#define OFF_CS     108032
#define SMEM_BYTES 108544

// ---------------------------------------------------------------------------
__device__ __forceinline__ void mma_s8(int* c,
                                       unsigned a0, unsigned a1, unsigned a2, unsigned a3,
                                       unsigned b0, unsigned b1) {
    asm volatile(
        "mma.sync.aligned.m16n8k32.row.col.s32.s8.s8.s32 "
        "{%0,%1,%2,%3}, {%4,%5,%6,%7}, {%8,%9}, {%0,%1,%2,%3};"
        : "+r"(c[0]), "+r"(c[1]), "+r"(c[2]), "+r"(c[3])
        : "r"(a0), "r"(a1), "r"(a2), "r"(a3), "r"(b0), "r"(b1));
}

__device__ __forceinline__ void ldsm4(unsigned& r0, unsigned& r1,
                                      unsigned& r2, unsigned& r3, uint32_t addr) {
    asm volatile("ldmatrix.sync.aligned.m8n8.x4.shared.b16 {%0,%1,%2,%3}, [%4];"
                 : "=r"(r0), "=r"(r1), "=r"(r2), "=r"(r3) : "r"(addr));
}

__device__ __forceinline__ void cp16(uint32_t dst, const void* src) {
    asm volatile("cp.async.cg.shared.global [%0], [%1], 16;" :: "r"(dst), "l"(src));
}

__device__ __forceinline__ uint32_t smem_u32(const void* p) {
    uint32_t a;
    asm("{ .reg .u64 t; cvta.to.shared.u64 t, %1; cvt.u32.u64 %0, t; }"
        : "=r"(a) : "l"(p));
    return a;
}

__device__ __forceinline__ float ex2f(float x) {
    float r;
    asm("ex2.approx.f32 %0, %1;" : "=f"(r) : "f"(x));
    return r;
}

// round(v.i * s) for |v*s| <= 127, bit-exact vs rintf: FADD at 1.5*2^23 rounds
// half-to-even; low byte of float bits IS the int8 (two's complement).
__device__ __forceinline__ unsigned pack_magic4(float4 v, float s) {
    unsigned b0 = __float_as_uint(__fadd_rn(__fmul_rn(v.x, s), MAGF));
    unsigned b1 = __float_as_uint(__fadd_rn(__fmul_rn(v.y, s), MAGF));
    unsigned b2 = __float_as_uint(__fadd_rn(__fmul_rn(v.z, s), MAGF));
    unsigned b3 = __float_as_uint(__fadd_rn(__fmul_rn(v.w, s), MAGF));
    unsigned r01 = __byte_perm(b0, b1, 0x0040);
    unsigned r23 = __byte_perm(b2, b3, 0x0040);
    return __byte_perm(r01, r23, 0x5410);
}

// exact int->float for |q| < 2^22 without I2F
__device__ __forceinline__ float i2f_magic(int q) {
    return __int_as_float(q + MAG_I) - MAGF;
}

// ---------------------------------------------------------------------------
// Kernel 1: weight ternarization (absmean scale) + zero normalizers.
// ---------------------------------------------------------------------------
__global__ void prep_kernel(const float* __restrict__ W1,
                            const float* __restrict__ W2) {
    __shared__ double red[1024];
    __shared__ float s_ws;
    const int tid = threadIdx.x;
    const float* W = (blockIdx.x == 0) ? W1 : W2;
    int8_t* Wq     = (blockIdx.x == 0) ? g_W1q : g_W2q;
    const int n    = (blockIdx.x == 0) ? 128 * 256 : 128 * 128;

    if (tid < 512) g_norm[blockIdx.x * 512 + tid] = 0.0;

    double acc = 0.0;
    for (int i = tid; i < n; i += 1024) acc += (double)fabsf(W[i]);
    red[tid] = acc;
    __syncthreads();
    for (int s = 512; s > 0; s >>= 1) {
        if (tid < s) red[tid] += red[tid + s];
        __syncthreads();
    }
    if (tid == 0) {
        float m  = fmaxf((float)(red[0] / (double)n), EPSF);
        s_ws = 1.0f / m;                 // ref: ws = 1/clip(mean)
        g_wsc[blockIdx.x] = m;           // ref's t/ws (t = +-1) -> t*m
    }
    __syncthreads();
    const float ws = s_ws;
    for (int i = tid; i < n; i += 1024) {
        float t = rintf(W[i] * ws);      // round half-to-even like jnp.round
        t = fminf(1.0f, fmaxf(-1.0f, t));
        Wq[i] = (int8_t)t;
    }
}

// ---------------------------------------------------------------------------
// Kernel 2: fused persistent pass. 296 CTAs, ~7 tiles each, 2 CTAs/SM.
// Per tile: warp-private quantize -> GEMM1 -> ReLU/requant -> GEMM2 ->
//           sigmoid -> pu store -> column sums. Warps sync only at csum flush.
// ---------------------------------------------------------------------------
__global__ __launch_bounds__(256, 2)
void bitnet_F(const float* __restrict__ evid, const float* __restrict__ prior,
              const float* __restrict__ b1, const float* __restrict__ b2,
              float* __restrict__ out) {
    extern __shared__ unsigned char sm[];
    const uint32_t sb = smem_u32(sm);
    const int tid   = threadIdx.x;
    const int lane  = tid & 31;
    const int w     = tid >> 5;
    const int g     = lane >> 2;   // mma group id (row)
    const int tg    = lane & 3;    // thread-in-group (col/k)
    const int mb    = w * 16;

    // ldmatrix per-lane address components
    const int lrow  = lane & 15;
    const int lkoff = (lane >> 4) * 16;
    const int brow  = ((lane >> 4) & 1) * 8 + (lane & 7);
    const int bkoff = ((lane >> 3) & 1) * 16;

    float* s1arr = (float*)(sm + OFF_S1);
    float* b1s   = (float*)(sm + OFF_B1);
    float* b2l   = (float*)(sm + OFF_B2L);
    float* csum  = (float*)(sm + OFF_CS);
    const float2* prior2 = (const float2*)prior;
    const float4* pr4 = (const float4*)prior;
    const float4* ev4 = (const float4*)evid;

    // ---- prologue: weight tiles once ----
#pragma unroll
    for (int i = 0; i < 8; i++) {            // W1: 2048 x 16B
        int c = tid + 256 * i;
        int o = c >> 4, k = c & 15;
        cp16(sb + OFF_W1 + o * W1_STR + k * 16, g_W1q + c * 16);
    }
#pragma unroll
    for (int i = 0; i < 4; i++) {            // W2: 1024 x 16B
        int c = tid + 256 * i;
        int o = c >> 3, k = c & 7;
        cp16(sb + OFF_W2 + o * W2_STR + k * 16, g_W2q + c * 16);
    }
    if (tid < 128) {
        csum[tid] = 0.0f;
        b1s[tid]  = __ldg(&b1[tid]);
        b2l[tid]  = -__ldg(&b2[tid]) * L2E;   // folded sigmoid bias
    }
    asm volatile("cp.async.commit_group;");
    asm volatile("cp.async.wait_group 0;" ::: "memory");
    __syncthreads();

    const float wsc1 = g_wsc[0];
    const float wsc2 = g_wsc[1];

    // tile-invariant LDSM bases
    const uint32_t aAbase  = sb + OFF_XQ + (mb + lrow) * XQ_STR + lkoff;
    const uint32_t aHbase  = sb + OFF_HQ + (mb + lrow) * HQ_STR + lkoff;
    const uint32_t bW1base = sb + OFF_W1 + brow * W1_STR + bkoff;
    const uint32_t bW2base = sb + OFF_W2 + brow * W2_STR + bkoff;

    for (int tile = blockIdx.x; tile < NTILES; tile += GRIDP) {
        const int token0 = tile * 128;
        const int batch  = token0 >> 15;

        // ---- Phase A: quantize own 16-row band (1 row/warp-iter, batch 4) ----
        {
            const size_t rbase = (size_t)(token0 + mb) * 32;   // float4 units
#pragma unroll
            for (int r0r = 0; r0r < 16; r0r += 4) {
                float4 pa[4], ea[4];
#pragma unroll
                for (int r = 0; r < 4; r++) {
                    pa[r] = __ldg(&pr4[rbase + (size_t)(r0r + r) * 32 + lane]);
                    ea[r] = __ldg(&ev4[rbase + (size_t)(r0r + r) * 32 + lane]);
                }
#pragma unroll
                for (int r = 0; r < 4; r++) {
                    float4 a = pa[r], b = ea[r];
                    float m = fmaxf(fmaxf(fabsf(a.x), fabsf(a.y)),
                                    fmaxf(fabsf(a.z), fabsf(a.w)));
                    m = fmaxf(m, fmaxf(fmaxf(fabsf(b.x), fabsf(b.y)),
                                       fmaxf(fabsf(b.z), fabsf(b.w))));
                    m = fmaxf(m, __shfl_xor_sync(0xffffffffu, m, 1));
                    m = fmaxf(m, __shfl_xor_sync(0xffffffffu, m, 2));
                    m = fmaxf(m, __shfl_xor_sync(0xffffffffu, m, 4));
                    m = fmaxf(m, __shfl_xor_sync(0xffffffffu, m, 8));
                    m = fmaxf(m, __shfl_xor_sync(0xffffffffu, m, 16));
                    float s = QBF / fmaxf(m, EPSF);
                    const int row = mb + r0r + r;
                    *(unsigned*)(sm + OFF_XQ + row * XQ_STR + lane * 4) =
                        pack_magic4(a, s);
                    *(unsigned*)(sm + OFF_XQ + row * XQ_STR + 128 + lane * 4) =
                        pack_magic4(b, s);
                    if (lane == 0) s1arr[row] = s;
                }
            }
        }
        __syncwarp();   // band + scales are warp-private

        // ---- GEMM1: [16 x 256] x [256 x 128] per warp, int8 exact ----
        int acc[16][4];
#pragma unroll
        for (int n = 0; n < 16; n++) { acc[n][0] = acc[n][1] = acc[n][2] = acc[n][3] = 0; }
#pragma unroll
        for (int k8 = 0; k8 < 8; k8++) {
            const int kb = k8 * 32;
            unsigned a0, a1, a2, a3;
            ldsm4(a0, a1, a2, a3, aAbase + kb);
#pragma unroll
            for (int n2 = 0; n2 < 8; n2++) {
                unsigned b0, b1r, b2r, b3;
                ldsm4(b0, b1r, b2r, b3, bW1base + (n2 * 16) * W1_STR + kb);
                mma_s8(acc[n2 * 2],     a0, a1, a2, a3, b0,  b1r);
                mma_s8(acc[n2 * 2 + 1], a0, a1, a2, a3, b2r, b3);
            }
        }

        // ---- Epilogue 1: dequant + bias + ReLU, quad absmax, magic requant ----
        const float dq0 = wsc1 / s1arr[mb + g];
        const float dq1 = wsc1 / s1arr[mb + g + 8];
        float hm0 = 0.0f, hm1 = 0.0f;
#pragma unroll
        for (int n = 0; n < 16; n++) {
            const int col = n * 8 + tg * 2;
            float c0 = fmaxf(0.0f, i2f_magic(acc[n][0]) * dq0 + b1s[col]);
            float c1 = fmaxf(0.0f, i2f_magic(acc[n][1]) * dq0 + b1s[col + 1]);
            float c2 = fmaxf(0.0f, i2f_magic(acc[n][2]) * dq1 + b1s[col]);
            float c3 = fmaxf(0.0f, i2f_magic(acc[n][3]) * dq1 + b1s[col + 1]);
            hm0 = fmaxf(hm0, fmaxf(c0, c1));
            hm1 = fmaxf(hm1, fmaxf(c2, c3));
            acc[n][0] = __float_as_int(c0);
            acc[n][1] = __float_as_int(c1);
            acc[n][2] = __float_as_int(c2);
            acc[n][3] = __float_as_int(c3);
        }
        hm0 = fmaxf(hm0, __shfl_xor_sync(0xffffffffu, hm0, 1));
        hm0 = fmaxf(hm0, __shfl_xor_sync(0xffffffffu, hm0, 2));
        hm1 = fmaxf(hm1, __shfl_xor_sync(0xffffffffu, hm1, 1));
        hm1 = fmaxf(hm1, __shfl_xor_sync(0xffffffffu, hm1, 2));
        const float s2_0 = QBF / fmaxf(hm0, EPSF);
        const float s2_1 = QBF / fmaxf(hm1, EPSF);

#pragma unroll
        for (int n = 0; n < 16; n++) {
            unsigned q0 = __float_as_uint(__fadd_rn(__fmul_rn(__int_as_float(acc[n][0]), s2_0), MAGF));
            unsigned q1 = __float_as_uint(__fadd_rn(__fmul_rn(__int_as_float(acc[n][1]), s2_0), MAGF));
            unsigned q2 = __float_as_uint(__fadd_rn(__fmul_rn(__int_as_float(acc[n][2]), s2_1), MAGF));
            unsigned q3 = __float_as_uint(__fadd_rn(__fmul_rn(__int_as_float(acc[n][3]), s2_1), MAGF));
            unsigned short p0 = (unsigned short)__byte_perm(q0, q1, 0x0040);
            unsigned short p1 = (unsigned short)__byte_perm(q2, q3, 0x0040);
            *(unsigned short*)(sm + OFF_HQ + (mb + g)     * HQ_STR + n * 8 + tg * 2) = p0;
            *(unsigned short*)(sm + OFF_HQ + (mb + g + 8) * HQ_STR + n * 8 + tg * 2) = p1;
        }
        __syncwarp();   // each warp reads only its own 16 HQ rows

        // ---- GEMM2: [16 x 128] x [128 x 128] per warp ----
#pragma unroll
        for (int n = 0; n < 16; n++) { acc[n][0] = acc[n][1] = acc[n][2] = acc[n][3] = 0; }
#pragma unroll
        for (int k4 = 0; k4 < 4; k4++) {
            const int kb = k4 * 32;
            unsigned a0, a1, a2, a3;
            ldsm4(a0, a1, a2, a3, aHbase + kb);
#pragma unroll
            for (int n2 = 0; n2 < 8; n2++) {
                unsigned b0, b1r, b2r, b3;
                ldsm4(b0, b1r, b2r, b3, bW2base + (n2 * 16) * W2_STR + kb);
                mma_s8(acc[n2 * 2],     a0, a1, a2, a3, b0,  b1r);
                mma_s8(acc[n2 * 2 + 1], a0, a1, a2, a3, b2r, b3);
            }
        }

        // ---- Epilogue 2: folded sigmoid (ex2 + fast div), store, col sums ----
        const float dq20 = wsc2 / s2_0;
        const float dq21 = wsc2 / s2_1;
        const float dql0 = -dq20 * L2E;     // exp(-z) = 2^(acc*dql + b2l)
        const float dql1 = -dq21 * L2E;
        const size_t row0 = (size_t)(token0 + mb + g) * 128;
        const size_t row1 = row0 + (size_t)8 * 128;

#pragma unroll
        for (int n = 0; n < 16; n++) {
            const int col = n * 8 + tg * 2;
            float e0 = ex2f(i2f_magic(acc[n][0]) * dql0 + b2l[col]);
            float e1 = ex2f(i2f_magic(acc[n][1]) * dql0 + b2l[col + 1]);
            float e2 = ex2f(i2f_magic(acc[n][2]) * dql1 + b2l[col]);
            float e3 = ex2f(i2f_magic(acc[n][3]) * dql1 + b2l[col + 1]);
            float2 pr0 = __ldg(&prior2[(row0 + col) >> 1]);   // L2-hot (phase A)
            float2 pr1 = __ldg(&prior2[(row1 + col) >> 1]);
            float u0 = __fdividef(pr0.x, 1.0f + e0);
            float u1 = __fdividef(pr0.y, 1.0f + e1);
            float u2 = __fdividef(pr1.x, 1.0f + e2);
            float u3 = __fdividef(pr1.y, 1.0f + e3);
            *(float2*)(out + row0 + col) = make_float2(u0, u1);
            *(float2*)(out + row1 + col) = make_float2(u2, u3);
            float cs0 = u0 + u2, cs1 = u1 + u3;
            cs0 += __shfl_xor_sync(0xffffffffu, cs0, 4);
            cs0 += __shfl_xor_sync(0xffffffffu, cs0, 8);
            cs0 += __shfl_xor_sync(0xffffffffu, cs0, 16);
            cs1 += __shfl_xor_sync(0xffffffffu, cs1, 4);
            cs1 += __shfl_xor_sync(0xffffffffu, cs1, 8);
            cs1 += __shfl_xor_sync(0xffffffffu, cs1, 16);
            if (g == 0) {
                atomicAdd(&csum[col], cs0);
                atomicAdd(&csum[col + 1], cs1);
            }
        }
        __syncthreads();
        if (tid < 128) {
            atomicAdd(&g_norm[batch * 128 + tid], (double)csum[tid]);
            csum[tid] = 0.0f;
        }
        __syncthreads();   // csum reset visible before next tile's atomics
    }
}

// ---------------------------------------------------------------------------
__global__ void finalize_norm() {
    int i = threadIdx.x;  // 1024 threads
    g_rnorm[i] = 1.0f / fmaxf((float)g_norm[i], 1e-10f);
}

// ---------------------------------------------------------------------------
__global__ void normalize_kernel(float4* __restrict__ out4) {
    int i = blockIdx.x * 256 + threadIdx.x;    // 8,388,608 float4s
    int b  = i >> 20;                          // 2^20 float4 per batch
    int f4 = i & 31;                           // 32 float4 per feature row
    float4 r = *(const float4*)&g_rnorm[b * 128 + f4 * 4];
    float4 v = out4[i];
    v.x *= r.x; v.y *= r.y; v.z *= r.z; v.w *= r.w;
    out4[i] = v;
}

// ---------------------------------------------------------------------------
extern "C" void kernel_launch(void* const* d_in, const int* in_sizes, int n_in,
                              void* d_out, int out_size) {
    const float* evid  = (const float*)d_in[0];
    const float* prior = (const float*)d_in[1];
    const float* W1    = (const float*)d_in[2];
    const float* b1    = (const float*)d_in[3];
    const float* W2    = (const float*)d_in[4];
    const float* b2    = (const float*)d_in[5];
    float* out = (float*)d_out;

    cudaFuncSetAttribute(bitnet_F, cudaFuncAttributeMaxDynamicSharedMemorySize,
                         SMEM_BYTES);

    prep_kernel<<<2, 1024>>>(W1, W2);
    bitnet_F<<<GRIDP, 256, SMEM_BYTES>>>(evid, prior, b1, b2, out);
    finalize_norm<<<1, 1024>>>();
    normalize_kernel<<<out_size / 1024, 256>>>((float4*)out);
}